// round 1
// baseline (speedup 1.0000x reference)
#include <cuda_runtime.h>
#include <math.h>

#define B_ 16
#define L_ 256
#define H_ 512
#define NH_ 8
#define DH_ 64
#define NL_ 6
#define NTOK_ 10000
#define P_ 4
#define KW_ 9
#define DFF_ 2048
#define LP_ (L_ + 8)
#define BL_ (B_ * L_)

// ---------------- device scratch (no allocations allowed) ----------------
__device__ float g_h[BL_ * H_];
__device__ float g_hn[BL_ * H_];
__device__ float g_hpad[B_ * LP_ * H_];
__device__ float g_tmp[BL_ * H_];
__device__ float g_parent[BL_ * H_];
__device__ float g_child[BL_ * H_];
__device__ float g_head[B_ * L_ * L_];
__device__ float g_headT[B_ * L_ * L_];
__device__ float g_qkv[BL_ * 3 * H_];
__device__ float g_ctx[BL_ * H_];
__device__ float g_ff[BL_ * DFF_];
__device__ int   g_mask[BL_];

// ---------------- embed + mask ----------------
__global__ void embed_kernel(const int* __restrict__ x, const float* __restrict__ emb,
                             float* __restrict__ h, int* __restrict__ mask) {
    int r = blockIdx.x;
    int tok = x[r];
    if (threadIdx.x == 0) mask[r] = (tok != 0) ? 1 : 0;
    const float* e = emb + (long)tok * H_;
    float* o = h + (long)r * H_;
    o[threadIdx.x]       = e[threadIdx.x];
    o[threadIdx.x + 256] = e[threadIdx.x + 256];
}

// ---------------- masked zero-padded copy for conv ----------------
__global__ void pad_kernel(const float* __restrict__ h, const int* __restrict__ mask,
                           float* __restrict__ hpad) {
    int b = blockIdx.x / LP_;
    int lp = blockIdx.x % LP_;
    int l = lp - 4;
    bool valid = (l >= 0 && l < L_) && (mask[b * L_ + l] != 0);
    float* dst = hpad + (long)blockIdx.x * H_;
    const float* src = h + (long)(b * L_ + l) * H_;
    for (int c = threadIdx.x; c < H_; c += blockDim.x)
        dst[c] = valid ? src[c] : 0.f;
}

// ---------------- conv1d as 9 accumulated GEMMs ----------------
// out[b,l,co] = bias[co] + sum_{k,ci} hpad[b,l+k,ci] * W[k,ci,co]
__global__ void conv_gemm_kernel(const float* __restrict__ hpad, const float* __restrict__ W,
                                 const float* __restrict__ bias, float* __restrict__ C) {
    __shared__ float As[16][65];
    __shared__ float Bs[16][65];
    int tx = threadIdx.x & 15, ty = threadIdx.x >> 4;
    int row0 = blockIdx.y * 64, col0 = blockIdx.x * 64;
    float acc[4][4] = {};

    int mA = threadIdx.x >> 2;
    int tA = (threadIdx.x & 3) * 4;
    int rA = row0 + mA;
    int bA = rA >> 8;
    int lA = rA & 255;
    int tB = threadIdx.x >> 4;
    int nB = (threadIdx.x & 15) * 4;

    for (int k = 0; k < KW_; k++) {
        const float* arow = hpad + ((long)(bA * LP_ + lA + k)) * H_ + tA;
        const float* wk = W + (long)k * H_ * H_ + (long)tB * H_ + col0 + nB;
        for (int c0 = 0; c0 < H_; c0 += 16) {
            float4 va = *(const float4*)(arow + c0);
            As[tA + 0][mA] = va.x; As[tA + 1][mA] = va.y;
            As[tA + 2][mA] = va.z; As[tA + 3][mA] = va.w;
            float4 vb = *(const float4*)(wk + (long)c0 * H_);
            Bs[tB][nB] = vb.x; Bs[tB][nB + 1] = vb.y;
            Bs[tB][nB + 2] = vb.z; Bs[tB][nB + 3] = vb.w;
            __syncthreads();
#pragma unroll
            for (int t = 0; t < 16; t++) {
                float a[4], bb[4];
#pragma unroll
                for (int i = 0; i < 4; i++) a[i] = As[t][ty + 16 * i];
#pragma unroll
                for (int j = 0; j < 4; j++) bb[j] = Bs[t][tx + 16 * j];
#pragma unroll
                for (int i = 0; i < 4; i++)
#pragma unroll
                    for (int j = 0; j < 4; j++)
                        acc[i][j] = fmaf(a[i], bb[j], acc[i][j]);
            }
            __syncthreads();
        }
    }
#pragma unroll
    for (int i = 0; i < 4; i++) {
        int r = row0 + ty + 16 * i;
#pragma unroll
        for (int j = 0; j < 4; j++) {
            int c = col0 + tx + 16 * j;
            C[(long)r * H_ + c] = acc[i][j] + bias[c];
        }
    }
}

// ---------------- generic GEMM: C = A(M,K) * W(N,K)^T (+bias)(+resid)(epilogue) ----------------
// epilogue: 0 = none, 1 = leaky_relu(0.01)
__global__ void gemm_kernel(const float* __restrict__ A, const float* __restrict__ W,
                            const float* __restrict__ bias, const float* __restrict__ resid,
                            float* __restrict__ C,
                            int M, int N, int Kd,
                            long sA, long sB, long sC, int epilogue) {
    int bz = blockIdx.z;
    A += (long)bz * sA;
    W += (long)bz * sB;
    C += (long)bz * sC;
    if (resid) resid += (long)bz * sC;

    __shared__ float As[16][65];
    __shared__ float Bs[16][65];
    int tx = threadIdx.x & 15, ty = threadIdx.x >> 4;
    int row0 = blockIdx.y * 64, col0 = blockIdx.x * 64;
    float acc[4][4] = {};

    int mA = threadIdx.x >> 2;
    int tA = (threadIdx.x & 3) * 4;
    int grA = row0 + mA;
    int nB = threadIdx.x >> 2;
    int tB = (threadIdx.x & 3) * 4;
    int gnB = col0 + nB;

    for (int k0 = 0; k0 < Kd; k0 += 16) {
        float4 va = make_float4(0.f, 0.f, 0.f, 0.f);
        if (grA < M) va = *(const float4*)(A + (long)grA * Kd + k0 + tA);
        As[tA + 0][mA] = va.x; As[tA + 1][mA] = va.y;
        As[tA + 2][mA] = va.z; As[tA + 3][mA] = va.w;

        float4 vb = make_float4(0.f, 0.f, 0.f, 0.f);
        if (gnB < N) vb = *(const float4*)(W + (long)gnB * Kd + k0 + tB);
        Bs[tB + 0][nB] = vb.x; Bs[tB + 1][nB] = vb.y;
        Bs[tB + 2][nB] = vb.z; Bs[tB + 3][nB] = vb.w;
        __syncthreads();
#pragma unroll
        for (int t = 0; t < 16; t++) {
            float a[4], bb[4];
#pragma unroll
            for (int i = 0; i < 4; i++) a[i] = As[t][ty + 16 * i];
#pragma unroll
            for (int j = 0; j < 4; j++) bb[j] = Bs[t][tx + 16 * j];
#pragma unroll
            for (int i = 0; i < 4; i++)
#pragma unroll
                for (int j = 0; j < 4; j++)
                    acc[i][j] = fmaf(a[i], bb[j], acc[i][j]);
        }
        __syncthreads();
    }
#pragma unroll
    for (int i = 0; i < 4; i++) {
        int r = row0 + ty + 16 * i;
        if (r >= M) continue;
#pragma unroll
        for (int j = 0; j < 4; j++) {
            int c = col0 + tx + 16 * j;
            if (c >= N) continue;
            float v = acc[i][j];
            if (bias) v += bias[c];
            if (epilogue == 1) v = (v > 0.f) ? v : 0.01f * v;
            if (resid) v += resid[(long)r * N + c];
            C[(long)r * N + c] = v;
        }
    }
}

// ---------------- layernorm (optional affine, optional tanh), row = 512 ----------------
__device__ __forceinline__ float block_sum_8w(float v, float* red) {
    int lane = threadIdx.x & 31, w = threadIdx.x >> 5;
#pragma unroll
    for (int o = 16; o; o >>= 1) v += __shfl_xor_sync(0xffffffffu, v, o);
    if (lane == 0) red[w] = v;
    __syncthreads();
    float t = (lane < 8) ? red[lane] : 0.f;
#pragma unroll
    for (int o = 4; o; o >>= 1) t += __shfl_xor_sync(0xffffffffu, t, o);
    return __shfl_sync(0xffffffffu, t, 0);
}

__global__ void ln_kernel(const float* __restrict__ in, float* __restrict__ out,
                          const float* __restrict__ s, const float* __restrict__ b,
                          int do_tanh) {
    __shared__ float red[32];
    long r = blockIdx.x;
    const float* x = in + r * H_;
    float v0 = x[threadIdx.x];
    float v1 = x[threadIdx.x + 256];
    float sum = block_sum_8w(v0 + v1, red);
    float m = sum * (1.f / 512.f);
    float d0 = v0 - m, d1 = v1 - m;
    __syncthreads();
    float var = block_sum_8w(d0 * d0 + d1 * d1, red) * (1.f / 512.f);
    float inv = rsqrtf(var + 1e-5f);
    float y0 = d0 * inv, y1 = d1 * inv;
    if (s) {
        y0 = y0 * s[threadIdx.x] + b[threadIdx.x];
        y1 = y1 * s[threadIdx.x + 256] + b[threadIdx.x + 256];
    }
    if (do_tanh) { y0 = tanhf(y0); y1 = tanhf(y1); }
    float* o = out + r * H_;
    o[threadIdx.x] = y0;
    o[threadIdx.x + 256] = y1;
}

// ---------------- parse softmax: mask -> *1/H -> softmax -> zero diag ----------------
__global__ void softmax_head_kernel(float* __restrict__ head, const int* __restrict__ mask) {
    __shared__ float red[32];
    int bi = blockIdx.x;
    int b = bi >> 8, i = bi & 255;
    float* row = head + (long)bi * L_;
    int j = threadIdx.x;
    float v = (mask[b * L_ + j] != 0) ? row[j] * (1.f / 512.f) : -INFINITY;

    int lane = threadIdx.x & 31, w = threadIdx.x >> 5;
    float m = v;
#pragma unroll
    for (int o = 16; o; o >>= 1) m = fmaxf(m, __shfl_xor_sync(0xffffffffu, m, o));
    if (lane == 0) red[w] = m;
    __syncthreads();
    float t = (lane < 8) ? red[lane] : -INFINITY;
#pragma unroll
    for (int o = 4; o; o >>= 1) t = fmaxf(t, __shfl_xor_sync(0xffffffffu, t, o));
    m = __shfl_sync(0xffffffffu, t, 0);
    __syncthreads();

    float e = (v == -INFINITY) ? 0.f : __expf(v - m);
    float sum = block_sum_8w(e, red);
    float p = (sum > 0.f) ? e / sum : 0.f;
    if (j == i) p = 0.f;
    row[j] = p;
}

// ---------------- head transpose (per batch) ----------------
__global__ void transpose_kernel(const float* __restrict__ head, float* __restrict__ headT) {
    __shared__ float t[32][33];
    int b = blockIdx.z;
    int i0 = blockIdx.y * 32, j0 = blockIdx.x * 32;
    const float* src = head + (long)b * L_ * L_;
    t[threadIdx.y][threadIdx.x] = src[(long)(i0 + threadIdx.y) * L_ + j0 + threadIdx.x];
    __syncthreads();
    headT[(long)b * L_ * L_ + (long)(j0 + threadIdx.y) * L_ + i0 + threadIdx.x] = t[threadIdx.x][threadIdx.y];
}

// ---------------- attention: per (b, head, 16-row q tile) ----------------
__global__ void attn_kernel(const float* __restrict__ qkv, const float* __restrict__ head,
                            const float* __restrict__ headT, const int* __restrict__ mask,
                            const float* __restrict__ relw, int layer,
                            float* __restrict__ ctx) {
    extern __shared__ float sm[];
    float* Ks = sm;                 // [256][65]
    float* Vs = Ks + 256 * 65;      // [256][64]
    float* Qs = Vs + 256 * 64;      // [16][64]
    float* Ps = Qs + 16 * 64;       // [16][256]

    int b = blockIdx.z, hh = blockIdx.y;
    int i0 = blockIdx.x * 16;
    const float* qbase = qkv + (long)b * L_ * (3 * H_) + hh * DH_;
    const float* kbase = qbase + H_;
    const float* vbase = qbase + 2 * H_;

    for (int idx = threadIdx.x; idx < 256 * 64; idx += blockDim.x) {
        int j = idx >> 6, d = idx & 63;
        Ks[j * 65 + d] = kbase[(long)j * (3 * H_) + d];
        Vs[idx]        = vbase[(long)j * (3 * H_) + d];
    }
    for (int idx = threadIdx.x; idx < 16 * 64; idx += blockDim.x) {
        int ii = idx >> 6, d = idx & 63;
        Qs[idx] = qbase[(long)(i0 + ii) * (3 * H_) + d];
    }
    __syncthreads();

    float a0 = relw[(layer * NH_ + hh) * 2 + 0];
    float a1 = relw[(layer * NH_ + hh) * 2 + 1];
    float mm = fmaxf(a0, a1);
    float e0 = __expf(a0 - mm), e1 = __expf(a1 - mm);
    float w0 = e0 / (e0 + e1), w1 = e1 / (e0 + e1);

    int warp = threadIdx.x >> 5, lane = threadIdx.x & 31;
    int i = i0 + warp;
    const float* hrow  = head  + ((long)b * L_ + i) * L_;
    const float* htrow = headT + ((long)b * L_ + i) * L_;
    const int* mrow = mask + b * L_;

    float p[8];
    float mx = -INFINITY;
#pragma unroll
    for (int t = 0; t < 8; t++) {
        int j = lane + 32 * t;
        float s = 0.f;
        const float* kr = Ks + j * 65;
        const float* qr = Qs + warp * 64;
#pragma unroll
        for (int d = 0; d < 64; d++) s = fmaf(qr[d], kr[d], s);
        s *= 0.125f;
        s += w0 * hrow[j] + w1 * htrow[j];
        if (!mrow[j]) s = -INFINITY;
        p[t] = s;
        mx = fmaxf(mx, s);
    }
#pragma unroll
    for (int o = 16; o; o >>= 1) mx = fmaxf(mx, __shfl_xor_sync(0xffffffffu, mx, o));
    float sum = 0.f;
#pragma unroll
    for (int t = 0; t < 8; t++) {
        float e = (p[t] == -INFINITY) ? 0.f : __expf(p[t] - mx);
        p[t] = e;
        sum += e;
    }
#pragma unroll
    for (int o = 16; o; o >>= 1) sum += __shfl_xor_sync(0xffffffffu, sum, o);
    float inv = (sum > 0.f) ? 1.f / sum : 0.f;
#pragma unroll
    for (int t = 0; t < 8; t++) Ps[warp * 256 + lane + 32 * t] = p[t] * inv;
    __syncthreads();

    for (int idx = threadIdx.x; idx < 16 * 64; idx += blockDim.x) {
        int r = idx >> 6, d = idx & 63;
        const float* pr = Ps + r * 256;
        float acc = 0.f;
#pragma unroll 8
        for (int j = 0; j < 256; j++) acc = fmaf(pr[j], Vs[j * 64 + d], acc);
        ctx[((long)(b * L_ + i0 + r)) * H_ + hh * DH_ + d] = acc;
    }
}

// ---------------- host orchestration ----------------
static inline void launch_gemm(const float* A, const float* W, const float* bias,
                               const float* resid, float* C,
                               int M, int N, int Kd, int epilogue,
                               int batch = 1, long sA = 0, long sB = 0, long sC = 0) {
    dim3 g((N + 63) / 64, (M + 63) / 64, batch);
    gemm_kernel<<<g, 256>>>(A, W, bias, resid, C, M, N, Kd, sA, sB, sC, epilogue);
}

extern "C" void kernel_launch(void* const* d_in, const int* in_sizes, int n_in,
                              void* d_out, int out_size) {
    const int*   x        = (const int*)d_in[0];
    // d_in[1] = pos (unused)
    const float* emb      = (const float*)d_in[2];
    const float* conv_w   = (const float*)d_in[3];
    const float* conv_b   = (const float*)d_in[4];
    const float* parent_w = (const float*)d_in[5];
    const float* parent_b = (const float*)d_in[6];
    const float* child_w  = (const float*)d_in[7];
    const float* child_b  = (const float*)d_in[8];
    const float* rel_w    = (const float*)d_in[9];
    const float* qkv_w    = (const float*)d_in[10];
    const float* qkv_b    = (const float*)d_in[11];
    const float* out_w    = (const float*)d_in[12];
    const float* out_b    = (const float*)d_in[13];
    const float* ln1_s    = (const float*)d_in[14];
    const float* ln1_b    = (const float*)d_in[15];
    const float* ln2_s    = (const float*)d_in[16];
    const float* ln2_b    = (const float*)d_in[17];
    const float* ff1_w    = (const float*)d_in[18];
    const float* ff1_b    = (const float*)d_in[19];
    const float* ff2_w    = (const float*)d_in[20];
    const float* ff2_b    = (const float*)d_in[21];
    const float* norm_s   = (const float*)d_in[22];
    const float* norm_b   = (const float*)d_in[23];
    const float* out_bias = (const float*)d_in[24];
    float* out = (float*)d_out;

    void *p;
    cudaGetSymbolAddress(&p, g_h);      float* h     = (float*)p;
    cudaGetSymbolAddress(&p, g_hn);     float* hn    = (float*)p;
    cudaGetSymbolAddress(&p, g_hpad);   float* hpad  = (float*)p;
    cudaGetSymbolAddress(&p, g_tmp);    float* tmp   = (float*)p;
    cudaGetSymbolAddress(&p, g_parent); float* par   = (float*)p;
    cudaGetSymbolAddress(&p, g_child);  float* chi   = (float*)p;
    cudaGetSymbolAddress(&p, g_head);   float* head  = (float*)p;
    cudaGetSymbolAddress(&p, g_headT);  float* headT = (float*)p;
    cudaGetSymbolAddress(&p, g_qkv);    float* qkv   = (float*)p;
    cudaGetSymbolAddress(&p, g_ctx);    float* ctx   = (float*)p;
    cudaGetSymbolAddress(&p, g_ff);     float* ff    = (float*)p;
    cudaGetSymbolAddress(&p, g_mask);   int*   mask  = (int*)p;

    int attn_smem = (256 * 65 + 256 * 64 + 16 * 64 + 16 * 256) * (int)sizeof(float);
    cudaFuncSetAttribute(attn_kernel, cudaFuncAttributeMaxDynamicSharedMemorySize, attn_smem);

    // ---- embedding + mask ----
    embed_kernel<<<BL_, 256>>>(x, emb, h, mask);

    // ---- parser: 4x (mask+pad -> conv -> LN(no affine) -> tanh) ----
    for (int pl = 0; pl < P_; pl++) {
        pad_kernel<<<B_ * LP_, 256>>>(h, mask, hpad);
        dim3 gconv(H_ / 64, BL_ / 64);
        conv_gemm_kernel<<<gconv, 256>>>(hpad, conv_w + (long)pl * KW_ * H_ * H_,
                                         conv_b + pl * H_, tmp);
        ln_kernel<<<BL_, 256>>>(tmp, h, nullptr, nullptr, 1);
    }

    // ---- parent / child projections ----
    launch_gemm(h, parent_w, parent_b, nullptr, par, BL_, H_, H_, 0);
    launch_gemm(h, child_w, child_b, nullptr, chi, BL_, H_, H_, 0);

    // ---- parse logits (batched) + softmax + diag zero + transpose ----
    launch_gemm(chi, par, nullptr, nullptr, head, L_, L_, H_, 0,
                B_, (long)L_ * H_, (long)L_ * H_, (long)L_ * L_);
    softmax_head_kernel<<<BL_, 256>>>(head, mask);
    transpose_kernel<<<dim3(8, 8, B_), dim3(32, 32)>>>(head, headT);

    // ---- transformer (h restarts from embeddings, unmasked) ----
    embed_kernel<<<BL_, 256>>>(x, emb, h, mask);
    for (int i = 0; i < NL_; i++) {
        ln_kernel<<<BL_, 256>>>(h, hn, ln1_s + i * H_, ln1_b + i * H_, 0);
        launch_gemm(hn, qkv_w + (long)i * 3 * H_ * H_, qkv_b + i * 3 * H_,
                    nullptr, qkv, BL_, 3 * H_, H_, 0);
        attn_kernel<<<dim3(L_ / 16, NH_, B_), 512, attn_smem>>>(qkv, head, headT, mask,
                                                                rel_w, i, ctx);
        launch_gemm(ctx, out_w + (long)i * H_ * H_, out_b + i * H_, h, h, BL_, H_, H_, 0);
        ln_kernel<<<BL_, 256>>>(h, hn, ln2_s + i * H_, ln2_b + i * H_, 0);
        launch_gemm(hn, ff1_w + (long)i * DFF_ * H_, ff1_b + i * DFF_,
                    nullptr, ff, BL_, DFF_, H_, 1);
        launch_gemm(ff, ff2_w + (long)i * H_ * DFF_, ff2_b + i * H_, h, h, BL_, H_, DFF_, 0);
    }

    // ---- final LN + tied-embedding output ----
    ln_kernel<<<BL_, 256>>>(h, hn, norm_s, norm_b, 0);
    launch_gemm(hn, emb, out_bias, nullptr, out, BL_, NTOK_, H_, 0);
}

// round 2
// speedup vs baseline: 1.9199x; 1.9199x over previous
#include <cuda_runtime.h>
#include <math.h>
#include <stdint.h>

#define B_ 16
#define L_ 256
#define H_ 512
#define NH_ 8
#define DH_ 64
#define NL_ 6
#define NTOK_ 10000
#define P_ 4
#define KW_ 9
#define DFF_ 2048
#define LP_ (L_ + 8)
#define BL_ (B_ * L_)

// ---------------- device scratch (no allocations allowed) ----------------
__device__ float g_h[BL_ * H_];
__device__ float g_hn[BL_ * H_];
__device__ float g_hpad[B_ * LP_ * H_];
__device__ float g_tmp[BL_ * H_];
__device__ float g_parent[BL_ * H_];
__device__ float g_child[BL_ * H_];
__device__ float g_head[B_ * L_ * L_];
__device__ float g_headT[B_ * L_ * L_];
__device__ float g_qkv[BL_ * 3 * H_];
__device__ float g_ctx[BL_ * H_];
__device__ float g_ff[BL_ * DFF_];
__device__ int   g_mask[BL_];

// ---------------- embed + mask ----------------
__global__ void embed_kernel(const int* __restrict__ x, const float* __restrict__ emb,
                             float* __restrict__ h, int* __restrict__ mask) {
    int r = blockIdx.x;
    int tok = x[r];
    if (threadIdx.x == 0) mask[r] = (tok != 0) ? 1 : 0;
    const float* e = emb + (long)tok * H_;
    float* o = h + (long)r * H_;
    o[threadIdx.x]       = e[threadIdx.x];
    o[threadIdx.x + 256] = e[threadIdx.x + 256];
}

// ---------------- masked zero-padded copy for conv ----------------
__global__ void pad_kernel(const float* __restrict__ h, const int* __restrict__ mask,
                           float* __restrict__ hpad) {
    int b = blockIdx.x / LP_;
    int lp = blockIdx.x % LP_;
    int l = lp - 4;
    bool valid = (l >= 0 && l < L_) && (mask[b * L_ + l] != 0);
    float* dst = hpad + (long)blockIdx.x * H_;
    const float* src = h + (long)(b * L_ + l) * H_;
    for (int c = threadIdx.x; c < H_; c += blockDim.x)
        dst[c] = valid ? src[c] : 0.f;
}

// =====================================================================
// tf32 tensor-core GEMM:  C = A(M,K) @ Bmat + bias (+leaky) (+resid)
//   transB=0: weight W is [N,K] row-major (Bmat = W^T)
//   transB=1: weight W is [K,N] row-major (Bmat = W)        (conv path)
//   conv_mode: A row m maps to hpad row (m>>8)*LP + (m&255), row stride=strideA
// Tiles: 128x128x32, 8 warps, warp tile 64x32 via mma.m16n8k8.tf32
// SMEM is stored in fragment-permuted order: A frag = 1x LDS.128, B = 1x LDS.64
// =====================================================================
#define BM 128
#define BN 128
#define KC 32
#define CHUNK_F 4096   // floats per (A or B) chunk buffer

__device__ __forceinline__ float to_tf32(float x) {
    float r;
    asm("cvt.rna.tf32.f32 %0, %1;" : "=f"(r) : "f"(x));
    return r;
}
__device__ __forceinline__ uint32_t fau(float x) { return __float_as_uint(x); }

__device__ __forceinline__ void mma_tf32(float c[4], uint32_t a0, uint32_t a1,
                                         uint32_t a2, uint32_t a3,
                                         uint32_t b0, uint32_t b1) {
    asm volatile(
        "mma.sync.aligned.m16n8k8.row.col.f32.tf32.tf32.f32 "
        "{%0,%1,%2,%3}, {%4,%5,%6,%7}, {%8,%9}, {%0,%1,%2,%3};\n"
        : "+f"(c[0]), "+f"(c[1]), "+f"(c[2]), "+f"(c[3])
        : "r"(a0), "r"(a1), "r"(a2), "r"(a3), "r"(b0), "r"(b1));
}

__global__ void gemm_tc(const float* __restrict__ A, const float* __restrict__ W,
                        const float* __restrict__ bias, const float* __restrict__ resid,
                        float* __restrict__ C,
                        int M, int N, int Kd, int strideA,
                        long sA, long sB, long sC,
                        int epilogue, int conv_mode, int transB) {
    extern __shared__ float smbuf[];
    float* Abuf = smbuf;                 // 2 * 4096
    float* Bbuf = smbuf + 2 * CHUNK_F;   // 2 * 4096

    int bz = blockIdx.z;
    A += (long)bz * sA;
    W += (long)bz * sB;
    C += (long)bz * sC;
    if (resid) resid += (long)bz * sC;

    const int tid = threadIdx.x;
    const int warp = tid >> 5, lane = tid & 31;
    const int wm = warp >> 2;            // 0..1
    const int wn = warp & 3;             // 0..3
    const int grp = lane >> 2, tig = lane & 3;
    const int row0 = blockIdx.y * BM;
    const int col0 = blockIdx.x * BN;

    float acc[4][4][4];
#pragma unroll
    for (int i = 0; i < 4; i++)
#pragma unroll
        for (int j = 0; j < 4; j++)
#pragma unroll
            for (int r = 0; r < 4; r++) acc[i][j][r] = 0.f;

    const int nchunks = Kd / KC;
    float4 a_ld[4], b_ld[4];

    // ---- global load of chunk c into registers ----
    auto ldg_chunk = [&](int c) {
        int k0 = c * KC;
#pragma unroll
        for (int it = 0; it < 4; it++) {
            int f4 = tid + 256 * it;
            int rit = f4 >> 3;          // row in A tile
            int c4 = f4 & 7;
            int arow = row0 + rit;
            long amap = conv_mode ? ((long)(arow >> 8) * LP_ + (arow & 255)) : (long)arow;
            a_ld[it] = *(const float4*)(A + amap * strideA + k0 + c4 * 4);
        }
        if (!transB) {
#pragma unroll
            for (int it = 0; it < 4; it++) {
                int f4 = tid + 256 * it;
                int rit = f4 >> 3;      // n in tile
                int c4 = f4 & 7;
                int n = col0 + rit;
                if (n < N)
                    b_ld[it] = *(const float4*)(W + (long)n * Kd + k0 + c4 * 4);
                else
                    b_ld[it] = make_float4(0.f, 0.f, 0.f, 0.f);
            }
        } else {
#pragma unroll
            for (int it = 0; it < 4; it++) {
                int f4 = tid + 256 * it;
                int kin = f4 >> 5;      // k row in tile (0..31)
                int c4 = f4 & 31;       // n float4 (0..31)
                b_ld[it] = *(const float4*)(W + (long)(k0 + kin) * N + col0 + c4 * 4);
            }
        }
    };

    // ---- store registers (tf32-converted) into permuted smem buffer ----
    auto sts_chunk = [&](int buf) {
        float* Ab = Abuf + buf * CHUNK_F;
        float* Bb = Bbuf + buf * CHUNK_F;
#pragma unroll
        for (int it = 0; it < 4; it++) {
            int f4 = tid + 256 * it;
            int rit = f4 >> 3;
            int c4 = f4 & 7;
            int ks = c4 >> 1;
            int mf = rit >> 4;
            int g = rit & 7;
            int r = ((rit >> 3) & 1) + 2 * (c4 & 1);
            int idx = ((ks * 8 + mf) * 32 + g * 4) * 4 + r;
            float4 v = a_ld[it];
            Ab[idx]      = to_tf32(v.x);
            Ab[idx + 4]  = to_tf32(v.y);
            Ab[idx + 8]  = to_tf32(v.z);
            Ab[idx + 12] = to_tf32(v.w);
        }
        if (!transB) {
#pragma unroll
            for (int it = 0; it < 4; it++) {
                int f4 = tid + 256 * it;
                int rit = f4 >> 3;
                int c4 = f4 & 7;
                int ks = c4 >> 1;
                int r = c4 & 1;
                int nf = rit >> 3;
                int g = rit & 7;
                int idx = ((ks * 16 + nf) * 32 + g * 4) * 2 + r;
                float4 v = b_ld[it];
                Bb[idx]     = to_tf32(v.x);
                Bb[idx + 2] = to_tf32(v.y);
                Bb[idx + 4] = to_tf32(v.z);
                Bb[idx + 6] = to_tf32(v.w);
            }
        } else {
#pragma unroll
            for (int it = 0; it < 4; it++) {
                int f4 = tid + 256 * it;
                int kin = f4 >> 5;
                int c4 = f4 & 31;
                int ks = kin >> 3;
                int kk = kin & 7;
                int tg = kk & 3;
                int r = kk >> 2;
                float v[4] = {b_ld[it].x, b_ld[it].y, b_ld[it].z, b_ld[it].w};
#pragma unroll
                for (int j = 0; j < 4; j++) {
                    int nin = c4 * 4 + j;
                    int nf = nin >> 3;
                    int g = nin & 7;
                    Bb[((ks * 16 + nf) * 32 + g * 4 + tg) * 2 + r] = to_tf32(v[j]);
                }
            }
        }
    };

    ldg_chunk(0);
    sts_chunk(0);
    __syncthreads();

    for (int c = 0; c < nchunks; c++) {
        if (c + 1 < nchunks) ldg_chunk(c + 1);

        const float* Ab = Abuf + (c & 1) * CHUNK_F;
        const float* Bb = Bbuf + (c & 1) * CHUNK_F;
#pragma unroll
        for (int ks = 0; ks < 4; ks++) {
            uint32_t a[4][4];
            uint32_t b[4][2];
#pragma unroll
            for (int mf = 0; mf < 4; mf++) {
                float4 v = *(const float4*)(Ab + ((ks * 8 + wm * 4 + mf) * 32 + lane) * 4);
                a[mf][0] = fau(v.x); a[mf][1] = fau(v.y);
                a[mf][2] = fau(v.z); a[mf][3] = fau(v.w);
            }
#pragma unroll
            for (int nf = 0; nf < 4; nf++) {
                float2 v = *(const float2*)(Bb + ((ks * 16 + wn * 4 + nf) * 32 + lane) * 2);
                b[nf][0] = fau(v.x); b[nf][1] = fau(v.y);
            }
#pragma unroll
            for (int mf = 0; mf < 4; mf++)
#pragma unroll
                for (int nf = 0; nf < 4; nf++)
                    mma_tf32(acc[mf][nf], a[mf][0], a[mf][1], a[mf][2], a[mf][3],
                             b[nf][0], b[nf][1]);
        }

        if (c + 1 < nchunks) {
            __syncthreads();
            sts_chunk((c + 1) & 1);
            __syncthreads();
        }
    }

    // ---- epilogue ----
#pragma unroll
    for (int mf = 0; mf < 4; mf++) {
        int r0 = row0 + wm * 64 + mf * 16 + grp;
        int r1 = r0 + 8;
#pragma unroll
        for (int nf = 0; nf < 4; nf++) {
            int cb = col0 + wn * 32 + nf * 8 + tig * 2;
            if (cb >= N) continue;
            float v0 = acc[mf][nf][0], v1 = acc[mf][nf][1];
            float v2 = acc[mf][nf][2], v3 = acc[mf][nf][3];
            if (bias) {
                float b0 = bias[cb], b1 = bias[cb + 1];
                v0 += b0; v1 += b1; v2 += b0; v3 += b1;
            }
            if (epilogue == 1) {
                v0 = (v0 > 0.f) ? v0 : 0.01f * v0;
                v1 = (v1 > 0.f) ? v1 : 0.01f * v1;
                v2 = (v2 > 0.f) ? v2 : 0.01f * v2;
                v3 = (v3 > 0.f) ? v3 : 0.01f * v3;
            }
            if (resid) {
                v0 += resid[(long)r0 * N + cb]; v1 += resid[(long)r0 * N + cb + 1];
                v2 += resid[(long)r1 * N + cb]; v3 += resid[(long)r1 * N + cb + 1];
            }
            *(float2*)(C + (long)r0 * N + cb) = make_float2(v0, v1);
            *(float2*)(C + (long)r1 * N + cb) = make_float2(v2, v3);
        }
    }
}

// ---------------- layernorm (optional affine, optional tanh), row = 512 ----------------
__device__ __forceinline__ float block_sum_8w(float v, float* red) {
    int lane = threadIdx.x & 31, w = threadIdx.x >> 5;
#pragma unroll
    for (int o = 16; o; o >>= 1) v += __shfl_xor_sync(0xffffffffu, v, o);
    if (lane == 0) red[w] = v;
    __syncthreads();
    float t = (lane < 8) ? red[lane] : 0.f;
#pragma unroll
    for (int o = 4; o; o >>= 1) t += __shfl_xor_sync(0xffffffffu, t, o);
    return __shfl_sync(0xffffffffu, t, 0);
}

__global__ void ln_kernel(const float* __restrict__ in, float* __restrict__ out,
                          const float* __restrict__ s, const float* __restrict__ b,
                          int do_tanh) {
    __shared__ float red[32];
    long r = blockIdx.x;
    const float* x = in + r * H_;
    float v0 = x[threadIdx.x];
    float v1 = x[threadIdx.x + 256];
    float sum = block_sum_8w(v0 + v1, red);
    float m = sum * (1.f / 512.f);
    float d0 = v0 - m, d1 = v1 - m;
    __syncthreads();
    float var = block_sum_8w(d0 * d0 + d1 * d1, red) * (1.f / 512.f);
    float inv = rsqrtf(var + 1e-5f);
    float y0 = d0 * inv, y1 = d1 * inv;
    if (s) {
        y0 = y0 * s[threadIdx.x] + b[threadIdx.x];
        y1 = y1 * s[threadIdx.x + 256] + b[threadIdx.x + 256];
    }
    if (do_tanh) { y0 = tanhf(y0); y1 = tanhf(y1); }
    float* o = out + r * H_;
    o[threadIdx.x] = y0;
    o[threadIdx.x + 256] = y1;
}

// ---------------- parse softmax: mask -> *1/H -> softmax -> zero diag ----------------
__global__ void softmax_head_kernel(float* __restrict__ head, const int* __restrict__ mask) {
    __shared__ float red[32];
    int bi = blockIdx.x;
    int b = bi >> 8, i = bi & 255;
    float* row = head + (long)bi * L_;
    int j = threadIdx.x;
    float v = (mask[b * L_ + j] != 0) ? row[j] * (1.f / 512.f) : -INFINITY;

    int lane = threadIdx.x & 31, w = threadIdx.x >> 5;
    float m = v;
#pragma unroll
    for (int o = 16; o; o >>= 1) m = fmaxf(m, __shfl_xor_sync(0xffffffffu, m, o));
    if (lane == 0) red[w] = m;
    __syncthreads();
    float t = (lane < 8) ? red[lane] : -INFINITY;
#pragma unroll
    for (int o = 4; o; o >>= 1) t = fmaxf(t, __shfl_xor_sync(0xffffffffu, t, o));
    m = __shfl_sync(0xffffffffu, t, 0);
    __syncthreads();

    float e = (v == -INFINITY) ? 0.f : __expf(v - m);
    float sum = block_sum_8w(e, red);
    float p = (sum > 0.f) ? e / sum : 0.f;
    if (j == i) p = 0.f;
    row[j] = p;
}

// ---------------- head transpose (per batch) ----------------
__global__ void transpose_kernel(const float* __restrict__ head, float* __restrict__ headT) {
    __shared__ float t[32][33];
    int b = blockIdx.z;
    int i0 = blockIdx.y * 32, j0 = blockIdx.x * 32;
    const float* src = head + (long)b * L_ * L_;
    t[threadIdx.y][threadIdx.x] = src[(long)(i0 + threadIdx.y) * L_ + j0 + threadIdx.x];
    __syncthreads();
    headT[(long)b * L_ * L_ + (long)(j0 + threadIdx.y) * L_ + i0 + threadIdx.x] = t[threadIdx.x][threadIdx.y];
}

// ---------------- attention: per (b, head, 16-row q tile) ----------------
__global__ void attn_kernel(const float* __restrict__ qkv, const float* __restrict__ head,
                            const float* __restrict__ headT, const int* __restrict__ mask,
                            const float* __restrict__ relw, int layer,
                            float* __restrict__ ctx) {
    extern __shared__ float sm[];
    float* Ks = sm;                 // [256][65]
    float* Vs = Ks + 256 * 65;      // [256][64]
    float* Qs = Vs + 256 * 64;      // [16][64]
    float* Ps = Qs + 16 * 64;       // [16][256]

    int b = blockIdx.z, hh = blockIdx.y;
    int i0 = blockIdx.x * 16;
    const float* qbase = qkv + (long)b * L_ * (3 * H_) + hh * DH_;
    const float* kbase = qbase + H_;
    const float* vbase = qbase + 2 * H_;

    for (int idx = threadIdx.x; idx < 256 * 64; idx += blockDim.x) {
        int j = idx >> 6, d = idx & 63;
        Ks[j * 65 + d] = kbase[(long)j * (3 * H_) + d];
        Vs[idx]        = vbase[(long)j * (3 * H_) + d];
    }
    for (int idx = threadIdx.x; idx < 16 * 64; idx += blockDim.x) {
        int ii = idx >> 6, d = idx & 63;
        Qs[idx] = qbase[(long)(i0 + ii) * (3 * H_) + d];
    }
    __syncthreads();

    float a0 = relw[(layer * NH_ + hh) * 2 + 0];
    float a1 = relw[(layer * NH_ + hh) * 2 + 1];
    float mm = fmaxf(a0, a1);
    float e0 = __expf(a0 - mm), e1 = __expf(a1 - mm);
    float w0 = e0 / (e0 + e1), w1 = e1 / (e0 + e1);

    int warp = threadIdx.x >> 5, lane = threadIdx.x & 31;
    int i = i0 + warp;
    const float* hrow  = head  + ((long)b * L_ + i) * L_;
    const float* htrow = headT + ((long)b * L_ + i) * L_;
    const int* mrow = mask + b * L_;

    float p[8];
    float mx = -INFINITY;
#pragma unroll
    for (int t = 0; t < 8; t++) {
        int j = lane + 32 * t;
        float s = 0.f;
        const float* kr = Ks + j * 65;
        const float* qr = Qs + warp * 64;
#pragma unroll
        for (int d = 0; d < 64; d++) s = fmaf(qr[d], kr[d], s);
        s *= 0.125f;
        s += w0 * hrow[j] + w1 * htrow[j];
        if (!mrow[j]) s = -INFINITY;
        p[t] = s;
        mx = fmaxf(mx, s);
    }
#pragma unroll
    for (int o = 16; o; o >>= 1) mx = fmaxf(mx, __shfl_xor_sync(0xffffffffu, mx, o));
    float sum = 0.f;
#pragma unroll
    for (int t = 0; t < 8; t++) {
        float e = (p[t] == -INFINITY) ? 0.f : __expf(p[t] - mx);
        p[t] = e;
        sum += e;
    }
#pragma unroll
    for (int o = 16; o; o >>= 1) sum += __shfl_xor_sync(0xffffffffu, sum, o);
    float inv = (sum > 0.f) ? 1.f / sum : 0.f;
#pragma unroll
    for (int t = 0; t < 8; t++) Ps[warp * 256 + lane + 32 * t] = p[t] * inv;
    __syncthreads();

    for (int idx = threadIdx.x; idx < 16 * 64; idx += blockDim.x) {
        int r = idx >> 6, d = idx & 63;
        const float* pr = Ps + r * 256;
        float acc = 0.f;
#pragma unroll 8
        for (int j = 0; j < 256; j++) acc = fmaf(pr[j], Vs[j * 64 + d], acc);
        ctx[((long)(b * L_ + i0 + r)) * H_ + hh * DH_ + d] = acc;
    }
}

// ---------------- host orchestration ----------------
static inline void launch_tc(const float* A, const float* W, const float* bias,
                             const float* resid, float* C,
                             int M, int N, int Kd, int epilogue,
                             int conv_mode = 0, int transB = 0, int strideA = -1,
                             int batch = 1, long sA = 0, long sB = 0, long sC = 0) {
    if (strideA < 0) strideA = Kd;
    dim3 g((N + BN - 1) / BN, (M + BM - 1) / BM, batch);
    int smem = 4 * CHUNK_F * (int)sizeof(float);
    gemm_tc<<<g, 256, smem>>>(A, W, bias, resid, C, M, N, Kd, strideA,
                              sA, sB, sC, epilogue, conv_mode, transB);
}

extern "C" void kernel_launch(void* const* d_in, const int* in_sizes, int n_in,
                              void* d_out, int out_size) {
    const int*   x        = (const int*)d_in[0];
    // d_in[1] = pos (unused)
    const float* emb      = (const float*)d_in[2];
    const float* conv_w   = (const float*)d_in[3];
    const float* conv_b   = (const float*)d_in[4];
    const float* parent_w = (const float*)d_in[5];
    const float* parent_b = (const float*)d_in[6];
    const float* child_w  = (const float*)d_in[7];
    const float* child_b  = (const float*)d_in[8];
    const float* rel_w    = (const float*)d_in[9];
    const float* qkv_w    = (const float*)d_in[10];
    const float* qkv_b    = (const float*)d_in[11];
    const float* out_w    = (const float*)d_in[12];
    const float* out_b    = (const float*)d_in[13];
    const float* ln1_s    = (const float*)d_in[14];
    const float* ln1_b    = (const float*)d_in[15];
    const float* ln2_s    = (const float*)d_in[16];
    const float* ln2_b    = (const float*)d_in[17];
    const float* ff1_w    = (const float*)d_in[18];
    const float* ff1_b    = (const float*)d_in[19];
    const float* ff2_w    = (const float*)d_in[20];
    const float* ff2_b    = (const float*)d_in[21];
    const float* norm_s   = (const float*)d_in[22];
    const float* norm_b   = (const float*)d_in[23];
    const float* out_bias = (const float*)d_in[24];
    float* out = (float*)d_out;

    void *p;
    cudaGetSymbolAddress(&p, g_h);      float* h     = (float*)p;
    cudaGetSymbolAddress(&p, g_hn);     float* hn    = (float*)p;
    cudaGetSymbolAddress(&p, g_hpad);   float* hpad  = (float*)p;
    cudaGetSymbolAddress(&p, g_tmp);    float* tmp   = (float*)p;
    cudaGetSymbolAddress(&p, g_parent); float* par   = (float*)p;
    cudaGetSymbolAddress(&p, g_child);  float* chi   = (float*)p;
    cudaGetSymbolAddress(&p, g_head);   float* head  = (float*)p;
    cudaGetSymbolAddress(&p, g_headT);  float* headT = (float*)p;
    cudaGetSymbolAddress(&p, g_qkv);    float* qkv   = (float*)p;
    cudaGetSymbolAddress(&p, g_ctx);    float* ctx   = (float*)p;
    cudaGetSymbolAddress(&p, g_ff);     float* ff    = (float*)p;
    cudaGetSymbolAddress(&p, g_mask);   int*   mask  = (int*)p;

    int attn_smem = (256 * 65 + 256 * 64 + 16 * 64 + 16 * 256) * (int)sizeof(float);
    cudaFuncSetAttribute(attn_kernel, cudaFuncAttributeMaxDynamicSharedMemorySize, attn_smem);
    int gemm_smem = 4 * CHUNK_F * (int)sizeof(float);
    cudaFuncSetAttribute(gemm_tc, cudaFuncAttributeMaxDynamicSharedMemorySize, gemm_smem);

    // ---- embedding + mask ----
    embed_kernel<<<BL_, 256>>>(x, emb, h, mask);

    // ---- parser: 4x (mask+pad -> conv(K=4608 GEMM) -> LN(no affine) -> tanh) ----
    for (int pl = 0; pl < P_; pl++) {
        pad_kernel<<<B_ * LP_, 256>>>(h, mask, hpad);
        launch_tc(hpad, conv_w + (long)pl * KW_ * H_ * H_, conv_b + pl * H_,
                  nullptr, tmp, BL_, H_, KW_ * H_, 0,
                  /*conv_mode=*/1, /*transB=*/1, /*strideA=*/H_);
        ln_kernel<<<BL_, 256>>>(tmp, h, nullptr, nullptr, 1);
    }

    // ---- parent / child projections ----
    launch_tc(h, parent_w, parent_b, nullptr, par, BL_, H_, H_, 0);
    launch_tc(h, child_w, child_b, nullptr, chi, BL_, H_, H_, 0);

    // ---- parse logits (batched) + softmax + diag zero + transpose ----
    launch_tc(chi, par, nullptr, nullptr, head, L_, L_, H_, 0, 0, 0, -1,
              B_, (long)L_ * H_, (long)L_ * H_, (long)L_ * L_);
    softmax_head_kernel<<<BL_, 256>>>(head, mask);
    transpose_kernel<<<dim3(8, 8, B_), dim3(32, 32)>>>(head, headT);

    // ---- transformer (h restarts from embeddings, unmasked) ----
    embed_kernel<<<BL_, 256>>>(x, emb, h, mask);
    for (int i = 0; i < NL_; i++) {
        ln_kernel<<<BL_, 256>>>(h, hn, ln1_s + i * H_, ln1_b + i * H_, 0);
        launch_tc(hn, qkv_w + (long)i * 3 * H_ * H_, qkv_b + i * 3 * H_,
                  nullptr, qkv, BL_, 3 * H_, H_, 0);
        attn_kernel<<<dim3(L_ / 16, NH_, B_), 512, attn_smem>>>(qkv, head, headT, mask,
                                                                rel_w, i, ctx);
        launch_tc(ctx, out_w + (long)i * H_ * H_, out_b + i * H_, h, h, BL_, H_, H_, 0);
        ln_kernel<<<BL_, 256>>>(h, hn, ln2_s + i * H_, ln2_b + i * H_, 0);
        launch_tc(hn, ff1_w + (long)i * DFF_ * H_, ff1_b + i * DFF_,
                  nullptr, ff, BL_, DFF_, H_, 1);
        launch_tc(ff, ff2_w + (long)i * H_ * DFF_, ff2_b + i * H_, h, h, BL_, H_, DFF_, 0);
    }

    // ---- final LN + tied-embedding output ----
    ln_kernel<<<BL_, 256>>>(h, hn, norm_s, norm_b, 0);
    launch_tc(hn, emb, out_bias, nullptr, out, BL_, NTOK_, H_, 0);
}

// round 4
// speedup vs baseline: 3.0226x; 1.5744x over previous
#include <cuda_runtime.h>
#include <cuda_fp16.h>
#include <math.h>
#include <stdint.h>

#define B_ 16
#define L_ 256
#define H_ 512
#define NH_ 8
#define DH_ 64
#define NL_ 6
#define NTOK_ 10000
#define P_ 4
#define KW_ 9
#define DFF_ 2048
#define LP_ (L_ + 8)
#define BL_ (B_ * L_)

// ---------------- device scratch (no allocations allowed) ----------------
__device__ float g_h[BL_ * H_];
__device__ float g_hn[BL_ * H_];
__device__ float g_hpad[B_ * LP_ * H_];
__device__ float g_tmp[BL_ * H_];
__device__ float g_parent[BL_ * H_];
__device__ float g_child[BL_ * H_];
__device__ float g_head[B_ * L_ * L_];
__device__ float g_headT[B_ * L_ * L_];
__device__ float g_qkv[BL_ * 3 * H_];
__device__ float g_ctx[BL_ * H_];
__device__ float g_ff[BL_ * DFF_];
__device__ int   g_mask[BL_];
__device__ float g_convT[P_ * H_ * KW_ * H_];   // conv weights -> [P][co][k*H+ci]

// ================= helpers =================
__device__ __forceinline__ uint32_t pack_h2(float x, float y) {
    __half2 h = __floats2half2_rn(x, y);        // low = x, high = y
    return *reinterpret_cast<uint32_t*>(&h);
}

// fp16 MMA, fp32 accumulate: D(16x8) += A(16x16) * B(16x8)
__device__ __forceinline__ void mma_f16(float c[4], uint32_t a0, uint32_t a1,
                                        uint32_t a2, uint32_t a3,
                                        uint32_t b0, uint32_t b1) {
    asm volatile(
        "mma.sync.aligned.m16n8k16.row.col.f32.f16.f16.f32 "
        "{%0,%1,%2,%3}, {%4,%5,%6,%7}, {%8,%9}, {%0,%1,%2,%3};\n"
        : "+f"(c[0]), "+f"(c[1]), "+f"(c[2]), "+f"(c[3])
        : "r"(a0), "r"(a1), "r"(a2), "r"(a3), "r"(b0), "r"(b1));
}

// =====================================================================
// fp16 tensor-core GEMM:  C = A(M,K) @ W(N,K)^T  (+bias)(+leaky)(+resid)
//   conv_mode: A row m -> hpad row (m>>8)*LP + (m&255), row stride strideA
// Tiles: 128x128x32, 8 warps (warp tile 64x32), mma.m16n8k16
// SMEM fragment-permuted: A frag = 1x LDS.128 (uint4), B frag = 1x LDS.64
//   A word idx = ((ks*8 + mf)*32 + l)*4 + w
//     value(l,w): row = mf*16 + (l>>2) + 8*(w&1), k = ks*16 + (l&3)*2 + 8*(w>>1) (+1)
//   B word idx = ((ks*16 + nf)*32 + l)*2 + w
//     value(l,w): n = nf*8 + (l>>2),   k = ks*16 + (l&3)*2 + 8*w (+1)
// =====================================================================
#define BM 128
#define BN 128
#define KC 32
#define A_WORDS 2048   // per buffer (uint32)
#define B_WORDS 2048

__global__ __launch_bounds__(256) void gemm_f16(
    const float* __restrict__ A, const float* __restrict__ W,
    const float* __restrict__ bias, const float* __restrict__ resid,
    float* __restrict__ C,
    int M, int N, int Kd, int strideA,
    long sA, long sB, long sC,
    int epilogue, int conv_mode)
{
    __shared__ uint32_t Abuf[2 * A_WORDS];
    __shared__ uint32_t Bbuf[2 * B_WORDS];

    int bz = blockIdx.z;
    A += (long)bz * sA;
    W += (long)bz * sB;
    C += (long)bz * sC;
    if (resid) resid += (long)bz * sC;

    const int tid = threadIdx.x;
    const int warp = tid >> 5, lane = tid & 31;
    const int wm = warp >> 2;            // 0..1
    const int wn = warp & 3;             // 0..3
    const int grp = lane >> 2, tig = lane & 3;
    const int row0 = blockIdx.y * BM;
    const int col0 = blockIdx.x * BN;

    float acc[4][4][4];
#pragma unroll
    for (int i = 0; i < 4; i++)
#pragma unroll
        for (int j = 0; j < 4; j++)
#pragma unroll
            for (int r = 0; r < 4; r++) acc[i][j][r] = 0.f;

    const int nchunks = Kd / KC;
    float4 a_ld[4], b_ld[4];

    // B producer fixed mapping: one seg per thread (128 rows x 2 k-halves)
    const int bseg_r = tid >> 1;         // n within tile
    const int bseg_h = tid & 1;          // which 16-k half
    const int bn = col0 + bseg_r;

    auto ldg_chunk = [&](int c) {
        const int k0 = c * KC;
#pragma unroll
        for (int it = 0; it < 4; it++) {
            int f4 = tid + 256 * it;
            int rit = f4 >> 3;
            int c4 = f4 & 7;
            int arow = row0 + rit;
            long amap = conv_mode ? ((long)(arow >> 8) * LP_ + (arow & 255)) : (long)arow;
            a_ld[it] = *(const float4*)(A + amap * (long)strideA + k0 + c4 * 4);
        }
        if (bn < N) {
            const float4* src = (const float4*)(W + (long)bn * Kd + k0 + bseg_h * 16);
#pragma unroll
            for (int it = 0; it < 4; it++) b_ld[it] = src[it];
        } else {
#pragma unroll
            for (int it = 0; it < 4; it++) b_ld[it] = make_float4(0.f, 0.f, 0.f, 0.f);
        }
    };

    auto sts_chunk = [&](int buf) {
        uint32_t* Ab = Abuf + buf * A_WORDS;
        uint32_t* Bb = Bbuf + buf * B_WORDS;
#pragma unroll
        for (int it = 0; it < 4; it++) {
            int f4 = tid + 256 * it;
            int rit = f4 >> 3;
            int c4 = f4 & 7;
            int mf = rit >> 4, rr = rit & 15;
            int lhi = rr & 7, wlo = rr >> 3;
            float v[4] = {a_ld[it].x, a_ld[it].y, a_ld[it].z, a_ld[it].w};
#pragma unroll
            for (int jj = 0; jj < 2; jj++) {
                int k = c4 * 4 + 2 * jj;
                int ks = k >> 4, kk = k & 15;
                int l = lhi * 4 + ((kk >> 1) & 3);
                int w = ((kk >> 3) << 1) | wlo;
                Ab[((ks * 8 + mf) * 32 + l) * 4 + w] = pack_h2(v[2 * jj], v[2 * jj + 1]);
            }
        }
        {
            int nf = bseg_r >> 3;
            int lhi = bseg_r & 7;
            int ks = bseg_h;
#pragma unroll
            for (int it = 0; it < 4; it++) {
                float v[4] = {b_ld[it].x, b_ld[it].y, b_ld[it].z, b_ld[it].w};
#pragma unroll
                for (int jj = 0; jj < 2; jj++) {
                    int cin = it * 4 + 2 * jj;        // k within the 16-k half
                    int l = lhi * 4 + ((cin >> 1) & 3);
                    int w = cin >> 3;
                    Bb[((ks * 16 + nf) * 32 + l) * 2 + w] = pack_h2(v[2 * jj], v[2 * jj + 1]);
                }
            }
        }
    };

    ldg_chunk(0);
    sts_chunk(0);
    __syncthreads();

    for (int c = 0; c < nchunks; c++) {
        if (c + 1 < nchunks) ldg_chunk(c + 1);

        const uint32_t* Ab = Abuf + (c & 1) * A_WORDS;
        const uint32_t* Bb = Bbuf + (c & 1) * B_WORDS;
#pragma unroll
        for (int ks = 0; ks < 2; ks++) {
            uint32_t a[4][4];
            uint32_t b[4][2];
#pragma unroll
            for (int mf = 0; mf < 4; mf++) {
                uint4 v = *(const uint4*)(Ab + ((ks * 8 + wm * 4 + mf) * 32 + lane) * 4);
                a[mf][0] = v.x; a[mf][1] = v.y; a[mf][2] = v.z; a[mf][3] = v.w;
            }
#pragma unroll
            for (int nf = 0; nf < 4; nf++) {
                uint2 v = *(const uint2*)(Bb + ((ks * 16 + wn * 4 + nf) * 32 + lane) * 2);
                b[nf][0] = v.x; b[nf][1] = v.y;
            }
#pragma unroll
            for (int mf = 0; mf < 4; mf++)
#pragma unroll
                for (int nf = 0; nf < 4; nf++)
                    mma_f16(acc[mf][nf], a[mf][0], a[mf][1], a[mf][2], a[mf][3],
                            b[nf][0], b[nf][1]);
        }

        if (c + 1 < nchunks) {
            __syncthreads();
            sts_chunk((c + 1) & 1);
            __syncthreads();
        }
    }

    // ---- epilogue ----
#pragma unroll
    for (int mf = 0; mf < 4; mf++) {
        int r0 = row0 + wm * 64 + mf * 16 + grp;
        int r1 = r0 + 8;
#pragma unroll
        for (int nf = 0; nf < 4; nf++) {
            int cb = col0 + wn * 32 + nf * 8 + tig * 2;
            if (cb >= N) continue;
            float v0 = acc[mf][nf][0], v1 = acc[mf][nf][1];
            float v2 = acc[mf][nf][2], v3 = acc[mf][nf][3];
            if (bias) {
                float b0 = bias[cb], b1 = bias[cb + 1];
                v0 += b0; v1 += b1; v2 += b0; v3 += b1;
            }
            if (epilogue == 1) {
                v0 = (v0 > 0.f) ? v0 : 0.01f * v0;
                v1 = (v1 > 0.f) ? v1 : 0.01f * v1;
                v2 = (v2 > 0.f) ? v2 : 0.01f * v2;
                v3 = (v3 > 0.f) ? v3 : 0.01f * v3;
            }
            if (resid) {
                v0 += resid[(long)r0 * N + cb]; v1 += resid[(long)r0 * N + cb + 1];
                v2 += resid[(long)r1 * N + cb]; v3 += resid[(long)r1 * N + cb + 1];
            }
            *(float2*)(C + (long)r0 * N + cb) = make_float2(v0, v1);
            *(float2*)(C + (long)r1 * N + cb) = make_float2(v2, v3);
        }
    }
}

// ---------------- conv weight transpose: w[p][k][ci][co] -> wt[p][co][k*H+ci] ----------------
__global__ void convw_transpose(const float* __restrict__ w, float* __restrict__ wt) {
    __shared__ float t[32][33];
    int pk = blockIdx.z;
    int p = pk / KW_, k = pk % KW_;
    int ci0 = blockIdx.y * 32, co0 = blockIdx.x * 32;
    t[threadIdx.y][threadIdx.x] =
        w[((long)pk * H_ + ci0 + threadIdx.y) * H_ + co0 + threadIdx.x];
    __syncthreads();
    wt[((long)p * H_ + co0 + threadIdx.y) * (KW_ * H_) + k * H_ + ci0 + threadIdx.x] =
        t[threadIdx.x][threadIdx.y];
}

// ---------------- embed + mask ----------------
__global__ void embed_kernel(const int* __restrict__ x, const float* __restrict__ emb,
                             float* __restrict__ h, int* __restrict__ mask) {
    int r = blockIdx.x;
    int tok = x[r];
    if (threadIdx.x == 0) mask[r] = (tok != 0) ? 1 : 0;
    const float* e = emb + (long)tok * H_;
    float* o = h + (long)r * H_;
    o[threadIdx.x]       = e[threadIdx.x];
    o[threadIdx.x + 256] = e[threadIdx.x + 256];
}

// ---------------- masked zero-padded copy for conv ----------------
__global__ void pad_kernel(const float* __restrict__ h, const int* __restrict__ mask,
                           float* __restrict__ hpad) {
    int b = blockIdx.x / LP_;
    int lp = blockIdx.x % LP_;
    int l = lp - 4;
    bool valid = (l >= 0 && l < L_) && (mask[b * L_ + l] != 0);
    float* dst = hpad + (long)blockIdx.x * H_;
    const float* src = h + (long)(b * L_ + l) * H_;
    for (int c = threadIdx.x; c < H_; c += blockDim.x)
        dst[c] = valid ? src[c] : 0.f;
}

// ---------------- layernorm ----------------
__device__ __forceinline__ float block_sum_8w(float v, float* red) {
    int lane = threadIdx.x & 31, w = threadIdx.x >> 5;
#pragma unroll
    for (int o = 16; o; o >>= 1) v += __shfl_xor_sync(0xffffffffu, v, o);
    if (lane == 0) red[w] = v;
    __syncthreads();
    float t = (lane < 8) ? red[lane] : 0.f;
#pragma unroll
    for (int o = 4; o; o >>= 1) t += __shfl_xor_sync(0xffffffffu, t, o);
    return __shfl_sync(0xffffffffu, t, 0);
}

__global__ void ln_kernel(const float* __restrict__ in, float* __restrict__ out,
                          const float* __restrict__ s, const float* __restrict__ b,
                          int do_tanh) {
    __shared__ float red[32];
    long r = blockIdx.x;
    const float* x = in + r * H_;
    float v0 = x[threadIdx.x];
    float v1 = x[threadIdx.x + 256];
    float sum = block_sum_8w(v0 + v1, red);
    float m = sum * (1.f / 512.f);
    float d0 = v0 - m, d1 = v1 - m;
    __syncthreads();
    float var = block_sum_8w(d0 * d0 + d1 * d1, red) * (1.f / 512.f);
    float inv = rsqrtf(var + 1e-5f);
    float y0 = d0 * inv, y1 = d1 * inv;
    if (s) {
        y0 = y0 * s[threadIdx.x] + b[threadIdx.x];
        y1 = y1 * s[threadIdx.x + 256] + b[threadIdx.x + 256];
    }
    if (do_tanh) { y0 = tanhf(y0); y1 = tanhf(y1); }
    float* o = out + r * H_;
    o[threadIdx.x] = y0;
    o[threadIdx.x + 256] = y1;
}

// ---------------- parse softmax ----------------
__global__ void softmax_head_kernel(float* __restrict__ head, const int* __restrict__ mask) {
    __shared__ float red[32];
    int bi = blockIdx.x;
    int b = bi >> 8, i = bi & 255;
    float* row = head + (long)bi * L_;
    int j = threadIdx.x;
    float v = (mask[b * L_ + j] != 0) ? row[j] * (1.f / 512.f) : -INFINITY;

    int lane = threadIdx.x & 31, w = threadIdx.x >> 5;
    float m = v;
#pragma unroll
    for (int o = 16; o; o >>= 1) m = fmaxf(m, __shfl_xor_sync(0xffffffffu, m, o));
    if (lane == 0) red[w] = m;
    __syncthreads();
    float t = (lane < 8) ? red[lane] : -INFINITY;
#pragma unroll
    for (int o = 4; o; o >>= 1) t = fmaxf(t, __shfl_xor_sync(0xffffffffu, t, o));
    m = __shfl_sync(0xffffffffu, t, 0);
    __syncthreads();

    float e = (v == -INFINITY) ? 0.f : __expf(v - m);
    float sum = block_sum_8w(e, red);
    float p = (sum > 0.f) ? e / sum : 0.f;
    if (j == i) p = 0.f;
    row[j] = p;
}

// ---------------- head transpose ----------------
__global__ void transpose_kernel(const float* __restrict__ head, float* __restrict__ headT) {
    __shared__ float t[32][33];
    int b = blockIdx.z;
    int i0 = blockIdx.y * 32, j0 = blockIdx.x * 32;
    const float* src = head + (long)b * L_ * L_;
    t[threadIdx.y][threadIdx.x] = src[(long)(i0 + threadIdx.y) * L_ + j0 + threadIdx.x];
    __syncthreads();
    headT[(long)b * L_ * L_ + (long)(j0 + threadIdx.y) * L_ + i0 + threadIdx.x] =
        t[threadIdx.x][threadIdx.y];
}

// ---------------- attention ----------------
__global__ void attn_kernel(const float* __restrict__ qkv, const float* __restrict__ head,
                            const float* __restrict__ headT, const int* __restrict__ mask,
                            const float* __restrict__ relw, int layer,
                            float* __restrict__ ctx) {
    extern __shared__ float sm[];
    float* Ks = sm;
    float* Vs = Ks + 256 * 65;
    float* Qs = Vs + 256 * 64;
    float* Ps = Qs + 16 * 64;

    int b = blockIdx.z, hh = blockIdx.y;
    int i0 = blockIdx.x * 16;
    const float* qbase = qkv + (long)b * L_ * (3 * H_) + hh * DH_;
    const float* kbase = qbase + H_;
    const float* vbase = qbase + 2 * H_;

    for (int idx = threadIdx.x; idx < 256 * 64; idx += blockDim.x) {
        int j = idx >> 6, d = idx & 63;
        Ks[j * 65 + d] = kbase[(long)j * (3 * H_) + d];
        Vs[idx]        = vbase[(long)j * (3 * H_) + d];
    }
    for (int idx = threadIdx.x; idx < 16 * 64; idx += blockDim.x) {
        int ii = idx >> 6, d = idx & 63;
        Qs[idx] = qbase[(long)(i0 + ii) * (3 * H_) + d];
    }
    __syncthreads();

    float a0 = relw[(layer * NH_ + hh) * 2 + 0];
    float a1 = relw[(layer * NH_ + hh) * 2 + 1];
    float mm = fmaxf(a0, a1);
    float e0 = __expf(a0 - mm), e1 = __expf(a1 - mm);
    float w0 = e0 / (e0 + e1), w1 = e1 / (e0 + e1);

    int warp = threadIdx.x >> 5, lane = threadIdx.x & 31;
    int i = i0 + warp;
    const float* hrow  = head  + ((long)b * L_ + i) * L_;
    const float* htrow = headT + ((long)b * L_ + i) * L_;
    const int* mrow = mask + b * L_;

    float p[8];
    float mx = -INFINITY;
#pragma unroll
    for (int t = 0; t < 8; t++) {
        int j = lane + 32 * t;
        float s = 0.f;
        const float* kr = Ks + j * 65;
        const float* qr = Qs + warp * 64;
#pragma unroll
        for (int d = 0; d < 64; d++) s = fmaf(qr[d], kr[d], s);
        s *= 0.125f;
        s += w0 * hrow[j] + w1 * htrow[j];
        if (!mrow[j]) s = -INFINITY;
        p[t] = s;
        mx = fmaxf(mx, s);
    }
#pragma unroll
    for (int o = 16; o; o >>= 1) mx = fmaxf(mx, __shfl_xor_sync(0xffffffffu, mx, o));
    float sum = 0.f;
#pragma unroll
    for (int t = 0; t < 8; t++) {
        float e = (p[t] == -INFINITY) ? 0.f : __expf(p[t] - mx);
        p[t] = e;
        sum += e;
    }
#pragma unroll
    for (int o = 16; o; o >>= 1) sum += __shfl_xor_sync(0xffffffffu, sum, o);
    float inv = (sum > 0.f) ? 1.f / sum : 0.f;
#pragma unroll
    for (int t = 0; t < 8; t++) Ps[warp * 256 + lane + 32 * t] = p[t] * inv;
    __syncthreads();

    for (int idx = threadIdx.x; idx < 16 * 64; idx += blockDim.x) {
        int r = idx >> 6, d = idx & 63;
        const float* pr = Ps + r * 256;
        float acc = 0.f;
#pragma unroll 8
        for (int j = 0; j < 256; j++) acc = fmaf(pr[j], Vs[j * 64 + d], acc);
        ctx[((long)(b * L_ + i0 + r)) * H_ + hh * DH_ + d] = acc;
    }
}

// ---------------- host orchestration ----------------
static inline void launch_hm(const float* A, const float* W, const float* bias,
                             const float* resid, float* C,
                             int M, int N, int Kd, int epilogue,
                             int conv_mode = 0, int strideA = -1,
                             int batch = 1, long sA = 0, long sB = 0, long sC = 0) {
    if (strideA < 0) strideA = Kd;
    dim3 g((N + BN - 1) / BN, (M + BM - 1) / BM, batch);
    gemm_f16<<<g, 256>>>(A, W, bias, resid, C, M, N, Kd, strideA,
                         sA, sB, sC, epilogue, conv_mode);
}

extern "C" void kernel_launch(void* const* d_in, const int* in_sizes, int n_in,
                              void* d_out, int out_size) {
    const int*   x        = (const int*)d_in[0];
    const float* emb      = (const float*)d_in[2];
    const float* conv_w   = (const float*)d_in[3];
    const float* conv_b   = (const float*)d_in[4];
    const float* parent_w = (const float*)d_in[5];
    const float* parent_b = (const float*)d_in[6];
    const float* child_w  = (const float*)d_in[7];
    const float* child_b  = (const float*)d_in[8];
    const float* rel_w    = (const float*)d_in[9];
    const float* qkv_w    = (const float*)d_in[10];
    const float* qkv_b    = (const float*)d_in[11];
    const float* out_w    = (const float*)d_in[12];
    const float* out_b    = (const float*)d_in[13];
    const float* ln1_s    = (const float*)d_in[14];
    const float* ln1_b    = (const float*)d_in[15];
    const float* ln2_s    = (const float*)d_in[16];
    const float* ln2_b    = (const float*)d_in[17];
    const float* ff1_w    = (const float*)d_in[18];
    const float* ff1_b    = (const float*)d_in[19];
    const float* ff2_w    = (const float*)d_in[20];
    const float* ff2_b    = (const float*)d_in[21];
    const float* norm_s   = (const float*)d_in[22];
    const float* norm_b   = (const float*)d_in[23];
    const float* out_bias = (const float*)d_in[24];
    float* out = (float*)d_out;

    void *p;
    cudaGetSymbolAddress(&p, g_h);      float* h     = (float*)p;
    cudaGetSymbolAddress(&p, g_hn);     float* hn    = (float*)p;
    cudaGetSymbolAddress(&p, g_hpad);   float* hpad  = (float*)p;
    cudaGetSymbolAddress(&p, g_tmp);    float* tmp   = (float*)p;
    cudaGetSymbolAddress(&p, g_parent); float* par   = (float*)p;
    cudaGetSymbolAddress(&p, g_child);  float* chi   = (float*)p;
    cudaGetSymbolAddress(&p, g_head);   float* head  = (float*)p;
    cudaGetSymbolAddress(&p, g_headT);  float* headT = (float*)p;
    cudaGetSymbolAddress(&p, g_qkv);    float* qkv   = (float*)p;
    cudaGetSymbolAddress(&p, g_ctx);    float* ctx   = (float*)p;
    cudaGetSymbolAddress(&p, g_ff);     float* ff    = (float*)p;
    cudaGetSymbolAddress(&p, g_mask);   int*   mask  = (int*)p;
    cudaGetSymbolAddress(&p, g_convT);  float* convT = (float*)p;

    int attn_smem = (256 * 65 + 256 * 64 + 16 * 64 + 16 * 256) * (int)sizeof(float);
    cudaFuncSetAttribute(attn_kernel, cudaFuncAttributeMaxDynamicSharedMemorySize, attn_smem);

    // ---- conv weight transpose (once per call) ----
    convw_transpose<<<dim3(16, 16, P_ * KW_), dim3(32, 32)>>>(conv_w, convT);

    // ---- embedding + mask ----
    embed_kernel<<<BL_, 256>>>(x, emb, h, mask);

    // ---- parser: 4x (mask+pad -> conv(K=4608 GEMM) -> LN(no affine) -> tanh) ----
    for (int pl = 0; pl < P_; pl++) {
        pad_kernel<<<B_ * LP_, 256>>>(h, mask, hpad);
        launch_hm(hpad, convT + (long)pl * H_ * KW_ * H_, conv_b + pl * H_,
                  nullptr, tmp, BL_, H_, KW_ * H_, 0,
                  /*conv_mode=*/1, /*strideA=*/H_);
        ln_kernel<<<BL_, 256>>>(tmp, h, nullptr, nullptr, 1);
    }

    // ---- parent / child projections ----
    launch_hm(h, parent_w, parent_b, nullptr, par, BL_, H_, H_, 0);
    launch_hm(h, child_w, child_b, nullptr, chi, BL_, H_, H_, 0);

    // ---- parse logits (batched) + softmax + diag zero + transpose ----
    launch_hm(chi, par, nullptr, nullptr, head, L_, L_, H_, 0, 0, -1,
              B_, (long)L_ * H_, (long)L_ * H_, (long)L_ * L_);
    softmax_head_kernel<<<BL_, 256>>>(head, mask);
    transpose_kernel<<<dim3(8, 8, B_), dim3(32, 32)>>>(head, headT);

    // ---- transformer ----
    embed_kernel<<<BL_, 256>>>(x, emb, h, mask);
    for (int i = 0; i < NL_; i++) {
        ln_kernel<<<BL_, 256>>>(h, hn, ln1_s + i * H_, ln1_b + i * H_, 0);
        launch_hm(hn, qkv_w + (long)i * 3 * H_ * H_, qkv_b + i * 3 * H_,
                  nullptr, qkv, BL_, 3 * H_, H_, 0);
        attn_kernel<<<dim3(L_ / 16, NH_, B_), 512, attn_smem>>>(qkv, head, headT, mask,
                                                                rel_w, i, ctx);
        launch_hm(ctx, out_w + (long)i * H_ * H_, out_b + i * H_, h, h, BL_, H_, H_, 0);
        ln_kernel<<<BL_, 256>>>(h, hn, ln2_s + i * H_, ln2_b + i * H_, 0);
        launch_hm(hn, ff1_w + (long)i * DFF_ * H_, ff1_b + i * DFF_,
                  nullptr, ff, BL_, DFF_, H_, 1);
        launch_hm(ff, ff2_w + (long)i * H_ * DFF_, ff2_b + i * H_, h, h, BL_, H_, DFF_, 0);
    }

    // ---- final LN + tied-embedding output ----
    ln_kernel<<<BL_, 256>>>(h, hn, norm_s, norm_b, 0);
    launch_hm(hn, emb, out_bias, nullptr, out, BL_, NTOK_, H_, 0);
}

// round 5
// speedup vs baseline: 3.9238x; 1.2982x over previous
#include <cuda_runtime.h>
#include <cuda_fp16.h>
#include <math.h>
#include <stdint.h>

#define B_ 16
#define L_ 256
#define H_ 512
#define NH_ 8
#define DH_ 64
#define NL_ 6
#define NTOK_ 10000
#define P_ 4
#define KW_ 9
#define DFF_ 2048
#define LP_ (L_ + 8)
#define BL_ (B_ * L_)

// ---------------- device scratch ----------------
__device__ float g_h[BL_ * H_];
__device__ float g_hn[BL_ * H_];
__device__ float g_hpad[B_ * LP_ * H_];
__device__ float g_tmp[BL_ * H_];
__device__ float g_parent[BL_ * H_];
__device__ float g_child[BL_ * H_];
__device__ float g_head[B_ * L_ * L_];
__device__ float g_headT[B_ * L_ * L_];
__device__ float g_qkv[BL_ * 3 * H_];
__device__ float g_ctx[BL_ * H_];
__device__ float g_ff[BL_ * DFF_];
__device__ int   g_mask[BL_];
__device__ float g_convT[P_ * H_ * KW_ * H_];

// ================= helpers =================
__device__ __forceinline__ uint32_t pack_h2(float x, float y) {
    __half2 h = __floats2half2_rn(x, y);
    return *reinterpret_cast<uint32_t*>(&h);
}
__device__ __forceinline__ uint32_t smem_u32(const void* p) {
    uint32_t a;
    asm("{ .reg .u64 t; cvta.to.shared.u64 t, %1; cvt.u32.u64 %0, t; }" : "=r"(a) : "l"(p));
    return a;
}
__device__ __forceinline__ uint32_t sw128(uint32_t x) { return x ^ ((x >> 3) & 0x70); }

__device__ __forceinline__ void mma_f16(float c[4], uint32_t a0, uint32_t a1,
                                        uint32_t a2, uint32_t a3,
                                        uint32_t b0, uint32_t b1) {
    asm volatile(
        "mma.sync.aligned.m16n8k16.row.col.f32.f16.f16.f32 "
        "{%0,%1,%2,%3}, {%4,%5,%6,%7}, {%8,%9}, {%0,%1,%2,%3};\n"
        : "+f"(c[0]), "+f"(c[1]), "+f"(c[2]), "+f"(c[3])
        : "r"(a0), "r"(a1), "r"(a2), "r"(a3), "r"(b0), "r"(b1));
}
__device__ __forceinline__ void ldsm_x4(uint32_t& r0, uint32_t& r1, uint32_t& r2,
                                        uint32_t& r3, uint32_t addr) {
    asm volatile("ldmatrix.sync.aligned.m8n8.x4.shared.b16 {%0,%1,%2,%3}, [%4];"
                 : "=r"(r0), "=r"(r1), "=r"(r2), "=r"(r3) : "r"(addr));
}
__device__ __forceinline__ void ldsm_x4_t(uint32_t& r0, uint32_t& r1, uint32_t& r2,
                                          uint32_t& r3, uint32_t addr) {
    asm volatile("ldmatrix.sync.aligned.m8n8.x4.trans.shared.b16 {%0,%1,%2,%3}, [%4];"
                 : "=r"(r0), "=r"(r1), "=r"(r2), "=r"(r3) : "r"(addr));
}

// =====================================================================
// fp16 tensor-core GEMM, templated tile config.
// BM = WM*MF*16 (=128), BN = WN*NF*8. C = A(M,K) @ W(N,K)^T (+bias)(+leaky)(+resid)
// =====================================================================
template <int WM, int WN, int MF, int NF>
__global__ __launch_bounds__(256) void gemm_f16_t(
    const float* __restrict__ A, const float* __restrict__ W,
    const float* __restrict__ bias, const float* __restrict__ resid,
    float* __restrict__ C,
    int M, int N, int Kd, int strideA,
    long sA, long sB, long sC,
    int epilogue, int conv_mode)
{
    constexpr int BMv = WM * MF * 16;
    constexpr int BNv = WN * NF * 8;
    constexpr int AW = 2 * (BMv / 16) * 32 * 4;   // words per A buffer
    constexpr int BW = 2 * (BNv / 8) * 32 * 2;    // words per B buffer
    __shared__ uint32_t Abuf[2 * AW];
    __shared__ uint32_t Bbuf[2 * BW];

    int bz = blockIdx.z;
    A += (long)bz * sA;
    W += (long)bz * sB;
    C += (long)bz * sC;
    if (resid) resid += (long)bz * sC;

    const int tid = threadIdx.x;
    const int warp = tid >> 5, lane = tid & 31;
    const int wm = warp / WN;
    const int wn = warp % WN;
    const int grp = lane >> 2, tig = lane & 3;
    const int row0 = blockIdx.y * BMv;
    const int col0 = blockIdx.x * BNv;

    float acc[MF][NF][4];
#pragma unroll
    for (int i = 0; i < MF; i++)
#pragma unroll
        for (int j = 0; j < NF; j++)
#pragma unroll
            for (int r = 0; r < 4; r++) acc[i][j][r] = 0.f;

    const int nchunks = Kd >> 5;   // KC = 32
    float4 a_ld[4], b_ld[4];

    const int nsegs = 2 * BNv;
    const int bseg_r = tid >> 1;
    const int bseg_h = tid & 1;
    const int bn = col0 + bseg_r;
    const bool bact = tid < nsegs;

    auto ldg_chunk = [&](int c) {
        const int k0 = c << 5;
#pragma unroll
        for (int it = 0; it < 4; it++) {
            int f4 = tid + 256 * it;
            int rit = f4 >> 3;
            int c4 = f4 & 7;
            int arow = row0 + rit;
            long amap = conv_mode ? ((long)(arow >> 8) * LP_ + (arow & 255)) : (long)arow;
            a_ld[it] = *(const float4*)(A + amap * (long)strideA + k0 + c4 * 4);
        }
        if (bact) {
            if (bn < N) {
                const float4* src = (const float4*)(W + (long)bn * Kd + k0 + bseg_h * 16);
#pragma unroll
                for (int it = 0; it < 4; it++) b_ld[it] = src[it];
            } else {
#pragma unroll
                for (int it = 0; it < 4; it++) b_ld[it] = make_float4(0.f, 0.f, 0.f, 0.f);
            }
        }
    };

    auto sts_chunk = [&](int buf) {
        uint32_t* Ab = Abuf + buf * AW;
        uint32_t* Bb = Bbuf + buf * BW;
#pragma unroll
        for (int it = 0; it < 4; it++) {
            int f4 = tid + 256 * it;
            int rit = f4 >> 3;
            int c4 = f4 & 7;
            int mfa = rit >> 4, rr = rit & 15;
            int lhi = rr & 7, wlo = rr >> 3;
            float v[4] = {a_ld[it].x, a_ld[it].y, a_ld[it].z, a_ld[it].w};
#pragma unroll
            for (int jj = 0; jj < 2; jj++) {
                int k = c4 * 4 + 2 * jj;
                int ks = k >> 4, kk = k & 15;
                int l = lhi * 4 + ((kk >> 1) & 3);
                int w = ((kk >> 3) << 1) | wlo;
                Ab[((ks * (BMv / 16) + mfa) * 32 + l) * 4 + w] =
                    pack_h2(v[2 * jj], v[2 * jj + 1]);
            }
        }
        if (bact) {
            int nfa = bseg_r >> 3;
            int lhi = bseg_r & 7;
            int ks = bseg_h;
#pragma unroll
            for (int it = 0; it < 4; it++) {
                float v[4] = {b_ld[it].x, b_ld[it].y, b_ld[it].z, b_ld[it].w};
#pragma unroll
                for (int jj = 0; jj < 2; jj++) {
                    int cin = it * 4 + 2 * jj;
                    int l = lhi * 4 + ((cin >> 1) & 3);
                    int w = cin >> 3;
                    Bb[((ks * (BNv / 8) + nfa) * 32 + l) * 2 + w] =
                        pack_h2(v[2 * jj], v[2 * jj + 1]);
                }
            }
        }
    };

    ldg_chunk(0);
    sts_chunk(0);
    __syncthreads();

    for (int c = 0; c < nchunks; c++) {
        if (c + 1 < nchunks) ldg_chunk(c + 1);

        const uint32_t* Ab = Abuf + (c & 1) * AW;
        const uint32_t* Bb = Bbuf + (c & 1) * BW;
#pragma unroll
        for (int ks = 0; ks < 2; ks++) {
            uint32_t a[MF][4];
            uint32_t b[NF][2];
#pragma unroll
            for (int mf = 0; mf < MF; mf++) {
                uint4 v = *(const uint4*)(Ab +
                    ((ks * (BMv / 16) + wm * MF + mf) * 32 + lane) * 4);
                a[mf][0] = v.x; a[mf][1] = v.y; a[mf][2] = v.z; a[mf][3] = v.w;
            }
#pragma unroll
            for (int nf = 0; nf < NF; nf++) {
                uint2 v = *(const uint2*)(Bb +
                    ((ks * (BNv / 8) + wn * NF + nf) * 32 + lane) * 2);
                b[nf][0] = v.x; b[nf][1] = v.y;
            }
#pragma unroll
            for (int mf = 0; mf < MF; mf++)
#pragma unroll
                for (int nf = 0; nf < NF; nf++)
                    mma_f16(acc[mf][nf], a[mf][0], a[mf][1], a[mf][2], a[mf][3],
                            b[nf][0], b[nf][1]);
        }

        if (c + 1 < nchunks) {
            __syncthreads();
            sts_chunk((c + 1) & 1);
            __syncthreads();
        }
    }

#pragma unroll
    for (int mf = 0; mf < MF; mf++) {
        int r0 = row0 + (wm * MF + mf) * 16 + grp;
        int r1 = r0 + 8;
#pragma unroll
        for (int nf = 0; nf < NF; nf++) {
            int cb = col0 + (wn * NF + nf) * 8 + tig * 2;
            if (cb >= N) continue;
            float v0 = acc[mf][nf][0], v1 = acc[mf][nf][1];
            float v2 = acc[mf][nf][2], v3 = acc[mf][nf][3];
            if (bias) {
                float b0 = bias[cb], b1 = bias[cb + 1];
                v0 += b0; v1 += b1; v2 += b0; v3 += b1;
            }
            if (epilogue == 1) {
                v0 = (v0 > 0.f) ? v0 : 0.01f * v0;
                v1 = (v1 > 0.f) ? v1 : 0.01f * v1;
                v2 = (v2 > 0.f) ? v2 : 0.01f * v2;
                v3 = (v3 > 0.f) ? v3 : 0.01f * v3;
            }
            if (resid) {
                v0 += resid[(long)r0 * N + cb]; v1 += resid[(long)r0 * N + cb + 1];
                v2 += resid[(long)r1 * N + cb]; v3 += resid[(long)r1 * N + cb + 1];
            }
            *(float2*)(C + (long)r0 * N + cb) = make_float2(v0, v1);
            *(float2*)(C + (long)r1 * N + cb) = make_float2(v2, v3);
        }
    }
}

// =====================================================================
// tensor-core attention: CTA = (64 q rows, head, batch), 256 threads
// =====================================================================
#define ATT_SM_Q 0
#define ATT_SM_K 8192
#define ATT_SM_V 40960
#define ATT_SM_P 73728
#define ATT_SM_RED 106496
#define ATT_SMEM (106496 + 2048)

__device__ __forceinline__ uint32_t swp(int r, int c2) {
    return (uint32_t)(r * 512 + (c2 ^ ((r & 7) << 4)));
}

__global__ __launch_bounds__(256) void attn_mma(
    const float* __restrict__ qkv, const float* __restrict__ head,
    const float* __restrict__ headT, const int* __restrict__ mask,
    const float* __restrict__ relw, int layer, float* __restrict__ ctx)
{
    extern __shared__ char sma[];
    uint32_t sbase = smem_u32(sma);
    const int b = blockIdx.z, hh = blockIdx.y, i0 = blockIdx.x * 64;
    const int tid = threadIdx.x, warp = tid >> 5, lane = tid & 31;
    const int wm = warp >> 2, wn = warp & 3;
    const int r4 = lane >> 2, c2 = (lane & 3) * 2;

    const float* qb = qkv + (long)b * L_ * 1536 + hh * 64;
    const float* kb = qb + 512;
    const float* vb = qb + 1024;

    // ---- load Q/K/V -> fp16 SW128 smem ----
    for (int idx = tid; idx < 64 * 16; idx += 256) {
        int r = idx >> 4, c4 = idx & 15;
        float4 v = *(const float4*)(qb + (long)(i0 + r) * 1536 + c4 * 4);
        *(uint2*)(sma + ATT_SM_Q + sw128(r * 128 + c4 * 8)) =
            make_uint2(pack_h2(v.x, v.y), pack_h2(v.z, v.w));
    }
    for (int idx = tid; idx < 256 * 16; idx += 256) {
        int r = idx >> 4, c4 = idx & 15;
        float4 v = *(const float4*)(kb + (long)r * 1536 + c4 * 4);
        *(uint2*)(sma + ATT_SM_K + sw128(r * 128 + c4 * 8)) =
            make_uint2(pack_h2(v.x, v.y), pack_h2(v.z, v.w));
        float4 u = *(const float4*)(vb + (long)r * 1536 + c4 * 4);
        *(uint2*)(sma + ATT_SM_V + sw128(r * 128 + c4 * 8)) =
            make_uint2(pack_h2(u.x, u.y), pack_h2(u.z, u.w));
    }
    __syncthreads();

    // ---- S = Q @ K^T : warp tile 32 rows x 64 cols ----
    float acc[2][8][4];
#pragma unroll
    for (int i = 0; i < 2; i++)
#pragma unroll
        for (int j = 0; j < 8; j++)
#pragma unroll
            for (int r = 0; r < 4; r++) acc[i][j][r] = 0.f;

#pragma unroll
    for (int kk = 0; kk < 4; kk++) {
        uint32_t a[2][4];
#pragma unroll
        for (int mf = 0; mf < 2; mf++) {
            int row = wm * 32 + mf * 16 + (lane & 7) + ((lane >> 3) & 1) * 8;
            int kh = (lane >> 4) & 1;
            ldsm_x4(a[mf][0], a[mf][1], a[mf][2], a[mf][3],
                    sbase + ATT_SM_Q + sw128(row * 128 + kk * 32 + kh * 16));
        }
        uint32_t bf[8][2];
#pragma unroll
        for (int ng = 0; ng < 4; ng++) {
            int nrow = wn * 64 + ng * 16 + (lane & 7) + ((lane >> 4) & 1) * 8;
            int kh = (lane >> 3) & 1;
            uint32_t r0, r1, r2, r3;
            ldsm_x4(r0, r1, r2, r3,
                    sbase + ATT_SM_K + sw128(nrow * 128 + kk * 32 + kh * 16));
            bf[2 * ng][0] = r0; bf[2 * ng][1] = r1;
            bf[2 * ng + 1][0] = r2; bf[2 * ng + 1][1] = r3;
        }
#pragma unroll
        for (int mf = 0; mf < 2; mf++)
#pragma unroll
            for (int nf = 0; nf < 8; nf++)
                mma_f16(acc[mf][nf], a[mf][0], a[mf][1], a[mf][2], a[mf][3],
                        bf[nf][0], bf[nf][1]);
    }

    // ---- rel weights ----
    float w0, w1;
    {
        float a0v = relw[(layer * NH_ + hh) * 2 + 0];
        float a1v = relw[(layer * NH_ + hh) * 2 + 1];
        float mv = fmaxf(a0v, a1v);
        float e0 = __expf(a0v - mv), e1 = __expf(a1v - mv);
        w0 = e0 / (e0 + e1); w1 = e1 / (e0 + e1);
    }

    // ---- bias + key-pad mask ----
#pragma unroll
    for (int nf = 0; nf < 8; nf++) {
        int j = wn * 64 + nf * 8 + c2;
        int m0 = mask[b * L_ + j], m1 = mask[b * L_ + j + 1];
#pragma unroll
        for (int mf = 0; mf < 2; mf++) {
            int ia = i0 + wm * 32 + mf * 16 + r4;
            float2 hd = *(const float2*)(head + ((long)(b * L_ + ia)) * L_ + j);
            float2 ht = *(const float2*)(headT + ((long)(b * L_ + ia)) * L_ + j);
            float s0 = acc[mf][nf][0] * 0.125f + w0 * hd.x + w1 * ht.x;
            float s1 = acc[mf][nf][1] * 0.125f + w0 * hd.y + w1 * ht.y;
            acc[mf][nf][0] = m0 ? s0 : -1e30f;
            acc[mf][nf][1] = m1 ? s1 : -1e30f;
            int ib = ia + 8;
            float2 hd2 = *(const float2*)(head + ((long)(b * L_ + ib)) * L_ + j);
            float2 ht2 = *(const float2*)(headT + ((long)(b * L_ + ib)) * L_ + j);
            float s2 = acc[mf][nf][2] * 0.125f + w0 * hd2.x + w1 * ht2.x;
            float s3 = acc[mf][nf][3] * 0.125f + w0 * hd2.y + w1 * ht2.y;
            acc[mf][nf][2] = m0 ? s2 : -1e30f;
            acc[mf][nf][3] = m1 ? s3 : -1e30f;
        }
    }

    // ---- softmax (register + cross-warp via smem) ----
    float* redm = (float*)(sma + ATT_SM_RED);   // [4][64]
    float* reds = redm + 256;                   // [4][64]
    float mx[4];
#pragma unroll
    for (int mf = 0; mf < 2; mf++)
#pragma unroll
        for (int hf = 0; hf < 2; hf++) {
            float m = -1e30f;
#pragma unroll
            for (int nf = 0; nf < 8; nf++)
                m = fmaxf(m, fmaxf(acc[mf][nf][2 * hf], acc[mf][nf][2 * hf + 1]));
            mx[mf * 2 + hf] = m;
        }
#pragma unroll
    for (int ri = 0; ri < 4; ri++) {
        mx[ri] = fmaxf(mx[ri], __shfl_xor_sync(0xffffffffu, mx[ri], 1));
        mx[ri] = fmaxf(mx[ri], __shfl_xor_sync(0xffffffffu, mx[ri], 2));
    }
    if ((lane & 3) == 0) {
#pragma unroll
        for (int mf = 0; mf < 2; mf++)
#pragma unroll
            for (int hf = 0; hf < 2; hf++)
                redm[wn * 64 + wm * 32 + mf * 16 + hf * 8 + r4] = mx[mf * 2 + hf];
    }
    __syncthreads();
    float MX[4];
#pragma unroll
    for (int mf = 0; mf < 2; mf++)
#pragma unroll
        for (int hf = 0; hf < 2; hf++) {
            int row = wm * 32 + mf * 16 + hf * 8 + r4;
            float m = redm[row];
            m = fmaxf(m, redm[64 + row]);
            m = fmaxf(m, redm[128 + row]);
            m = fmaxf(m, redm[192 + row]);
            MX[mf * 2 + hf] = m;
        }
    float sm[4] = {0.f, 0.f, 0.f, 0.f};
#pragma unroll
    for (int mf = 0; mf < 2; mf++)
#pragma unroll
        for (int nf = 0; nf < 8; nf++)
#pragma unroll
            for (int hf = 0; hf < 2; hf++) {
                float e0 = __expf(acc[mf][nf][2 * hf] - MX[mf * 2 + hf]);
                float e1 = __expf(acc[mf][nf][2 * hf + 1] - MX[mf * 2 + hf]);
                acc[mf][nf][2 * hf] = e0;
                acc[mf][nf][2 * hf + 1] = e1;
                sm[mf * 2 + hf] += e0 + e1;
            }
#pragma unroll
    for (int ri = 0; ri < 4; ri++) {
        sm[ri] += __shfl_xor_sync(0xffffffffu, sm[ri], 1);
        sm[ri] += __shfl_xor_sync(0xffffffffu, sm[ri], 2);
    }
    if ((lane & 3) == 0) {
#pragma unroll
        for (int mf = 0; mf < 2; mf++)
#pragma unroll
            for (int hf = 0; hf < 2; hf++)
                reds[wn * 64 + wm * 32 + mf * 16 + hf * 8 + r4] = sm[mf * 2 + hf];
    }
    __syncthreads();
    float inv[4];
#pragma unroll
    for (int mf = 0; mf < 2; mf++)
#pragma unroll
        for (int hf = 0; hf < 2; hf++) {
            int row = wm * 32 + mf * 16 + hf * 8 + r4;
            float t = reds[row] + reds[64 + row] + reds[128 + row] + reds[192 + row];
            inv[mf * 2 + hf] = 1.f / t;
        }

    // ---- P (normalized) -> fp16 smem ----
#pragma unroll
    for (int mf = 0; mf < 2; mf++)
#pragma unroll
        for (int nf = 0; nf < 8; nf++) {
            int rowa = wm * 32 + mf * 16 + r4;
            int j = wn * 64 + nf * 8 + c2;
            *(uint32_t*)(sma + ATT_SM_P + swp(rowa, j * 2)) =
                pack_h2(acc[mf][nf][0] * inv[mf * 2], acc[mf][nf][1] * inv[mf * 2]);
            *(uint32_t*)(sma + ATT_SM_P + swp(rowa + 8, j * 2)) =
                pack_h2(acc[mf][nf][2] * inv[mf * 2 + 1], acc[mf][nf][3] * inv[mf * 2 + 1]);
        }
    __syncthreads();

    // ---- O = P @ V : warp tile 32 rows x 16 d-cols ----
    float oacc[2][2][4];
#pragma unroll
    for (int i = 0; i < 2; i++)
#pragma unroll
        for (int j = 0; j < 2; j++)
#pragma unroll
            for (int r = 0; r < 4; r++) oacc[i][j][r] = 0.f;

#pragma unroll
    for (int kk = 0; kk < 16; kk++) {
        uint32_t a[2][4];
#pragma unroll
        for (int mf = 0; mf < 2; mf++) {
            int row = wm * 32 + mf * 16 + (lane & 7) + ((lane >> 3) & 1) * 8;
            int kh = (lane >> 4) & 1;
            ldsm_x4(a[mf][0], a[mf][1], a[mf][2], a[mf][3],
                    sbase + ATT_SM_P + swp(row, kk * 32 + kh * 16));
        }
        uint32_t bf[2][2];
        {
            int kvrow = kk * 16 + (lane & 7) + ((lane >> 3) & 1) * 8;
            int nb = wn * 16 + ((lane >> 4) & 1) * 8;
            uint32_t r0, r1, r2, r3;
            ldsm_x4_t(r0, r1, r2, r3,
                      sbase + ATT_SM_V + sw128(kvrow * 128 + nb * 2));
            bf[0][0] = r0; bf[0][1] = r1; bf[1][0] = r2; bf[1][1] = r3;
        }
#pragma unroll
        for (int mf = 0; mf < 2; mf++)
#pragma unroll
            for (int nf = 0; nf < 2; nf++)
                mma_f16(oacc[mf][nf], a[mf][0], a[mf][1], a[mf][2], a[mf][3],
                        bf[nf][0], bf[nf][1]);
    }

    // ---- write ctx ----
#pragma unroll
    for (int mf = 0; mf < 2; mf++)
#pragma unroll
        for (int nf = 0; nf < 2; nf++) {
            int row = i0 + wm * 32 + mf * 16 + r4;
            int d = wn * 16 + nf * 8 + c2;
            float* dst = ctx + ((long)(b * L_) + row) * H_ + hh * 64 + d;
            *(float2*)dst = make_float2(oacc[mf][nf][0], oacc[mf][nf][1]);
            *(float2*)(dst + 8 * H_) = make_float2(oacc[mf][nf][2], oacc[mf][nf][3]);
        }
}

// ---------------- conv weight transpose ----------------
__global__ void convw_transpose(const float* __restrict__ w, float* __restrict__ wt) {
    __shared__ float t[32][33];
    int pk = blockIdx.z;
    int p = pk / KW_, k = pk % KW_;
    int ci0 = blockIdx.y * 32, co0 = blockIdx.x * 32;
    t[threadIdx.y][threadIdx.x] =
        w[((long)pk * H_ + ci0 + threadIdx.y) * H_ + co0 + threadIdx.x];
    __syncthreads();
    wt[((long)p * H_ + co0 + threadIdx.y) * (KW_ * H_) + k * H_ + ci0 + threadIdx.x] =
        t[threadIdx.x][threadIdx.y];
}

// ---------------- embed + mask ----------------
__global__ void embed_kernel(const int* __restrict__ x, const float* __restrict__ emb,
                             float* __restrict__ h, int* __restrict__ mask) {
    int r = blockIdx.x;
    int tok = x[r];
    if (threadIdx.x == 0) mask[r] = (tok != 0) ? 1 : 0;
    const float* e = emb + (long)tok * H_;
    float* o = h + (long)r * H_;
    o[threadIdx.x]       = e[threadIdx.x];
    o[threadIdx.x + 256] = e[threadIdx.x + 256];
}

// ---------------- masked zero-padded copy for conv ----------------
__global__ void pad_kernel(const float* __restrict__ h, const int* __restrict__ mask,
                           float* __restrict__ hpad) {
    int b = blockIdx.x / LP_;
    int lp = blockIdx.x % LP_;
    int l = lp - 4;
    bool valid = (l >= 0 && l < L_) && (mask[b * L_ + l] != 0);
    float* dst = hpad + (long)blockIdx.x * H_;
    const float* src = h + (long)(b * L_ + l) * H_;
    for (int c = threadIdx.x; c < H_; c += blockDim.x)
        dst[c] = valid ? src[c] : 0.f;
}

// ---------------- layernorm ----------------
__device__ __forceinline__ float block_sum_8w(float v, float* red) {
    int lane = threadIdx.x & 31, w = threadIdx.x >> 5;
#pragma unroll
    for (int o = 16; o; o >>= 1) v += __shfl_xor_sync(0xffffffffu, v, o);
    if (lane == 0) red[w] = v;
    __syncthreads();
    float t = (lane < 8) ? red[lane] : 0.f;
#pragma unroll
    for (int o = 4; o; o >>= 1) t += __shfl_xor_sync(0xffffffffu, t, o);
    return __shfl_sync(0xffffffffu, t, 0);
}

__global__ void ln_kernel(const float* __restrict__ in, float* __restrict__ out,
                          const float* __restrict__ s, const float* __restrict__ b,
                          int do_tanh) {
    __shared__ float red[32];
    long r = blockIdx.x;
    const float* x = in + r * H_;
    float v0 = x[threadIdx.x];
    float v1 = x[threadIdx.x + 256];
    float sum = block_sum_8w(v0 + v1, red);
    float m = sum * (1.f / 512.f);
    float d0 = v0 - m, d1 = v1 - m;
    __syncthreads();
    float var = block_sum_8w(d0 * d0 + d1 * d1, red) * (1.f / 512.f);
    float inv = rsqrtf(var + 1e-5f);
    float y0 = d0 * inv, y1 = d1 * inv;
    if (s) {
        y0 = y0 * s[threadIdx.x] + b[threadIdx.x];
        y1 = y1 * s[threadIdx.x + 256] + b[threadIdx.x + 256];
    }
    if (do_tanh) { y0 = tanhf(y0); y1 = tanhf(y1); }
    float* o = out + r * H_;
    o[threadIdx.x] = y0;
    o[threadIdx.x + 256] = y1;
}

// ---------------- parse softmax ----------------
__global__ void softmax_head_kernel(float* __restrict__ head, const int* __restrict__ mask) {
    __shared__ float red[32];
    int bi = blockIdx.x;
    int b = bi >> 8, i = bi & 255;
    float* row = head + (long)bi * L_;
    int j = threadIdx.x;
    float v = (mask[b * L_ + j] != 0) ? row[j] * (1.f / 512.f) : -INFINITY;

    int lane = threadIdx.x & 31, w = threadIdx.x >> 5;
    float m = v;
#pragma unroll
    for (int o = 16; o; o >>= 1) m = fmaxf(m, __shfl_xor_sync(0xffffffffu, m, o));
    if (lane == 0) red[w] = m;
    __syncthreads();
    float t = (lane < 8) ? red[lane] : -INFINITY;
#pragma unroll
    for (int o = 4; o; o >>= 1) t = fmaxf(t, __shfl_xor_sync(0xffffffffu, t, o));
    m = __shfl_sync(0xffffffffu, t, 0);
    __syncthreads();

    float e = (v == -INFINITY) ? 0.f : __expf(v - m);
    float sum = block_sum_8w(e, red);
    float p = (sum > 0.f) ? e / sum : 0.f;
    if (j == i) p = 0.f;
    row[j] = p;
}

// ---------------- head transpose ----------------
__global__ void transpose_kernel(const float* __restrict__ head, float* __restrict__ headT) {
    __shared__ float t[32][33];
    int b = blockIdx.z;
    int i0 = blockIdx.y * 32, j0 = blockIdx.x * 32;
    const float* src = head + (long)b * L_ * L_;
    t[threadIdx.y][threadIdx.x] = src[(long)(i0 + threadIdx.y) * L_ + j0 + threadIdx.x];
    __syncthreads();
    headT[(long)b * L_ * L_ + (long)(j0 + threadIdx.y) * L_ + i0 + threadIdx.x] =
        t[threadIdx.x][threadIdx.y];
}

// ---------------- host orchestration ----------------
static inline void launch_hm(const float* A, const float* W, const float* bias,
                             const float* resid, float* C,
                             int M, int N, int Kd, int epilogue,
                             int conv_mode = 0, int strideA = -1,
                             int batch = 1, long sA = 0, long sB = 0, long sC = 0) {
    if (strideA < 0) strideA = Kd;
    if (N <= 512) {
        dim3 g((N + 63) / 64, M / 128, batch);
        gemm_f16_t<4, 2, 2, 4><<<g, 256>>>(A, W, bias, resid, C, M, N, Kd, strideA,
                                           sA, sB, sC, epilogue, conv_mode);
    } else {
        dim3 g((N + 127) / 128, M / 128, batch);
        gemm_f16_t<2, 4, 4, 4><<<g, 256>>>(A, W, bias, resid, C, M, N, Kd, strideA,
                                           sA, sB, sC, epilogue, conv_mode);
    }
}

extern "C" void kernel_launch(void* const* d_in, const int* in_sizes, int n_in,
                              void* d_out, int out_size) {
    const int*   x        = (const int*)d_in[0];
    const float* emb      = (const float*)d_in[2];
    const float* conv_w   = (const float*)d_in[3];
    const float* conv_b   = (const float*)d_in[4];
    const float* parent_w = (const float*)d_in[5];
    const float* parent_b = (const float*)d_in[6];
    const float* child_w  = (const float*)d_in[7];
    const float* child_b  = (const float*)d_in[8];
    const float* rel_w    = (const float*)d_in[9];
    const float* qkv_w    = (const float*)d_in[10];
    const float* qkv_b    = (const float*)d_in[11];
    const float* out_w    = (const float*)d_in[12];
    const float* out_b    = (const float*)d_in[13];
    const float* ln1_s    = (const float*)d_in[14];
    const float* ln1_b    = (const float*)d_in[15];
    const float* ln2_s    = (const float*)d_in[16];
    const float* ln2_b    = (const float*)d_in[17];
    const float* ff1_w    = (const float*)d_in[18];
    const float* ff1_b    = (const float*)d_in[19];
    const float* ff2_w    = (const float*)d_in[20];
    const float* ff2_b    = (const float*)d_in[21];
    const float* norm_s   = (const float*)d_in[22];
    const float* norm_b   = (const float*)d_in[23];
    const float* out_bias = (const float*)d_in[24];
    float* out = (float*)d_out;

    void *p;
    cudaGetSymbolAddress(&p, g_h);      float* h     = (float*)p;
    cudaGetSymbolAddress(&p, g_hn);     float* hn    = (float*)p;
    cudaGetSymbolAddress(&p, g_hpad);   float* hpad  = (float*)p;
    cudaGetSymbolAddress(&p, g_tmp);    float* tmp   = (float*)p;
    cudaGetSymbolAddress(&p, g_parent); float* par   = (float*)p;
    cudaGetSymbolAddress(&p, g_child);  float* chi   = (float*)p;
    cudaGetSymbolAddress(&p, g_head);   float* head  = (float*)p;
    cudaGetSymbolAddress(&p, g_headT);  float* headT = (float*)p;
    cudaGetSymbolAddress(&p, g_qkv);    float* qkv   = (float*)p;
    cudaGetSymbolAddress(&p, g_ctx);    float* ctx   = (float*)p;
    cudaGetSymbolAddress(&p, g_ff);     float* ff    = (float*)p;
    cudaGetSymbolAddress(&p, g_mask);   int*   mask  = (int*)p;
    cudaGetSymbolAddress(&p, g_convT);  float* convT = (float*)p;

    cudaFuncSetAttribute(attn_mma, cudaFuncAttributeMaxDynamicSharedMemorySize, ATT_SMEM);

    // ---- conv weight transpose ----
    convw_transpose<<<dim3(16, 16, P_ * KW_), dim3(32, 32)>>>(conv_w, convT);

    // ---- embedding + mask ----
    embed_kernel<<<BL_, 256>>>(x, emb, h, mask);

    // ---- parser ----
    for (int pl = 0; pl < P_; pl++) {
        pad_kernel<<<B_ * LP_, 256>>>(h, mask, hpad);
        launch_hm(hpad, convT + (long)pl * H_ * KW_ * H_, conv_b + pl * H_,
                  nullptr, tmp, BL_, H_, KW_ * H_, 0,
                  /*conv_mode=*/1, /*strideA=*/H_);
        ln_kernel<<<BL_, 256>>>(tmp, h, nullptr, nullptr, 1);
    }

    // ---- parent / child ----
    launch_hm(h, parent_w, parent_b, nullptr, par, BL_, H_, H_, 0);
    launch_hm(h, child_w, child_b, nullptr, chi, BL_, H_, H_, 0);

    // ---- parse logits + softmax + transpose ----
    launch_hm(chi, par, nullptr, nullptr, head, L_, L_, H_, 0, 0, -1,
              B_, (long)L_ * H_, (long)L_ * H_, (long)L_ * L_);
    softmax_head_kernel<<<BL_, 256>>>(head, mask);
    transpose_kernel<<<dim3(8, 8, B_), dim3(32, 32)>>>(head, headT);

    // ---- transformer ----
    embed_kernel<<<BL_, 256>>>(x, emb, h, mask);
    for (int i = 0; i < NL_; i++) {
        ln_kernel<<<BL_, 256>>>(h, hn, ln1_s + i * H_, ln1_b + i * H_, 0);
        launch_hm(hn, qkv_w + (long)i * 3 * H_ * H_, qkv_b + i * 3 * H_,
                  nullptr, qkv, BL_, 3 * H_, H_, 0);
        attn_mma<<<dim3(4, NH_, B_), 256, ATT_SMEM>>>(qkv, head, headT, mask,
                                                      rel_w, i, ctx);
        launch_hm(ctx, out_w + (long)i * H_ * H_, out_b + i * H_, h, h, BL_, H_, H_, 0);
        ln_kernel<<<BL_, 256>>>(h, hn, ln2_s + i * H_, ln2_b + i * H_, 0);
        launch_hm(hn, ff1_w + (long)i * DFF_ * H_, ff1_b + i * DFF_,
                  nullptr, ff, BL_, DFF_, H_, 1);
        launch_hm(ff, ff2_w + (long)i * H_ * DFF_, ff2_b + i * H_, h, h, BL_, H_, DFF_, 0);
    }

    // ---- final LN + tied output ----
    ln_kernel<<<BL_, 256>>>(h, hn, norm_s, norm_b, 0);
    launch_hm(hn, emb, out_bias, nullptr, out, BL_, NTOK_, H_, 0);
}

// round 6
// speedup vs baseline: 6.6902x; 1.7050x over previous
#include <cuda_runtime.h>
#include <cuda_fp16.h>
#include <math.h>
#include <stdint.h>

#define B_ 16
#define L_ 256
#define H_ 512
#define NH_ 8
#define DH_ 64
#define NL_ 6
#define NTOK_ 10000
#define P_ 4
#define KW_ 9
#define DFF_ 2048
#define LP_ (L_ + 8)
#define BL_ (B_ * L_)

// ---------------- device scratch (fp32) ----------------
__device__ float g_h[BL_ * H_];
__device__ float g_tmp[BL_ * H_];
__device__ float g_head[B_ * L_ * L_];
__device__ float g_headT[B_ * L_ * L_];
__device__ int   g_mask[BL_];
// ---------------- device scratch (fp16) ----------------
__device__ __half g_h16[BL_ * H_];
__device__ __half g_hn16[BL_ * H_];
__device__ __half g_hpad16[B_ * LP_ * H_];
__device__ __half g_par16[BL_ * H_];
__device__ __half g_chi16[BL_ * H_];
__device__ __half g_qkv16[BL_ * 3 * H_];
__device__ __half g_ctx16[BL_ * H_];
__device__ __half g_ff16[BL_ * DFF_];
// fp16 weights
__device__ __half g_convT16[P_ * H_ * KW_ * H_];
__device__ __half g_qkvw16[NL_ * 3 * H_ * H_];
__device__ __half g_outw16[NL_ * H_ * H_];
__device__ __half g_ff1w16[NL_ * DFF_ * H_];
__device__ __half g_ff2w16[NL_ * H_ * DFF_];
__device__ __half g_parw16[H_ * H_];
__device__ __half g_chiw16[H_ * H_];
__device__ __half g_emb16[NTOK_ * H_];

// ================= helpers =================
__device__ __forceinline__ uint32_t pack_h2(float x, float y) {
    __half2 h = __floats2half2_rn(x, y);
    return *reinterpret_cast<uint32_t*>(&h);
}
__device__ __forceinline__ uint32_t smem_u32(const void* p) {
    uint32_t a;
    asm("{ .reg .u64 t; cvta.to.shared.u64 t, %1; cvt.u32.u64 %0, t; }" : "=r"(a) : "l"(p));
    return a;
}
__device__ __forceinline__ uint32_t sw128(uint32_t x) { return x ^ ((x >> 3) & 0x70); }

__device__ __forceinline__ void mma_f16(float c[4], uint32_t a0, uint32_t a1,
                                        uint32_t a2, uint32_t a3,
                                        uint32_t b0, uint32_t b1) {
    asm volatile(
        "mma.sync.aligned.m16n8k16.row.col.f32.f16.f16.f32 "
        "{%0,%1,%2,%3}, {%4,%5,%6,%7}, {%8,%9}, {%0,%1,%2,%3};\n"
        : "+f"(c[0]), "+f"(c[1]), "+f"(c[2]), "+f"(c[3])
        : "r"(a0), "r"(a1), "r"(a2), "r"(a3), "r"(b0), "r"(b1));
}
__device__ __forceinline__ void ldsm_x4(uint32_t& r0, uint32_t& r1, uint32_t& r2,
                                        uint32_t& r3, uint32_t addr) {
    asm volatile("ldmatrix.sync.aligned.m8n8.x4.shared.b16 {%0,%1,%2,%3}, [%4];"
                 : "=r"(r0), "=r"(r1), "=r"(r2), "=r"(r3) : "r"(addr));
}
__device__ __forceinline__ void ldsm_x4_t(uint32_t& r0, uint32_t& r1, uint32_t& r2,
                                          uint32_t& r3, uint32_t addr) {
    asm volatile("ldmatrix.sync.aligned.m8n8.x4.trans.shared.b16 {%0,%1,%2,%3}, [%4];"
                 : "=r"(r0), "=r"(r1), "=r"(r2), "=r"(r3) : "r"(addr));
}

// ---------------- fp32 -> fp16 convert ----------------
__global__ void cvt_f2h(const float* __restrict__ src, __half* __restrict__ dst, int n4) {
    int i = blockIdx.x * 256 + threadIdx.x;
    if (i < n4) {
        float4 v = *(const float4*)(src + i * 4);
        *(uint2*)(dst + i * 4) = make_uint2(pack_h2(v.x, v.y), pack_h2(v.z, v.w));
    }
}

// conv weights: w[p][k][ci][co] -> wt16[p][co][k*H+ci]
__global__ void convw_transpose16(const float* __restrict__ w, __half* __restrict__ wt) {
    __shared__ float t[32][33];
    int pk = blockIdx.z;
    int p = pk / KW_, k = pk % KW_;
    int ci0 = blockIdx.y * 32, co0 = blockIdx.x * 32;
    t[threadIdx.y][threadIdx.x] =
        w[((long)pk * H_ + ci0 + threadIdx.y) * H_ + co0 + threadIdx.x];
    __syncthreads();
    wt[((long)p * H_ + co0 + threadIdx.y) * (KW_ * H_) + k * H_ + ci0 + threadIdx.x] =
        __float2half(t[threadIdx.x][threadIdx.y]);
}

// =====================================================================
// fp16 GEMM via SW128 rows + ldmatrix. C = A(M,K) @ W(N,K)^T
// K chunk = 64 halves (128B row). BM = WM*MF*16, BN = WN*NF*8.
// =====================================================================
template <int WM, int WN, int MF, int NF>
__global__ __launch_bounds__(256) void gemm_h(
    const __half* __restrict__ A, const __half* __restrict__ W,
    const float* __restrict__ bias, const float* __restrict__ resid,
    float* __restrict__ C, __half* __restrict__ C16,
    int M, int N, int Kd, int strideA,
    long sA, long sB, long sC,
    int epilogue, int conv_mode)
{
    constexpr int BM = WM * MF * 16;
    constexpr int BN = WN * NF * 8;
    constexpr int ABYTES = BM * 128;
    constexpr int BBYTES = BN * 128;
    constexpr int AIT = BM * 8 / 256;
    constexpr int BIT = BN * 8 / 256;

    extern __shared__ char smem[];
    char* Abuf = smem;
    char* Bbuf = smem + 2 * ABYTES;
    uint32_t sb = smem_u32(smem);

    int bz = blockIdx.z;
    A += (long)bz * sA;
    W += (long)bz * sB;
    if (C) C += (long)bz * sC;
    if (C16) C16 += (long)bz * sC;
    if (resid) resid += (long)bz * sC;

    const int tid = threadIdx.x;
    const int warp = tid >> 5, lane = tid & 31;
    const int wm = warp / WN;
    const int wn = warp % WN;
    const int grp = lane >> 2, tig = lane & 3;
    const int row0 = blockIdx.y * BM;
    const int col0 = blockIdx.x * BN;

    float acc[MF][NF][4];
#pragma unroll
    for (int i = 0; i < MF; i++)
#pragma unroll
        for (int j = 0; j < NF; j++)
#pragma unroll
            for (int r = 0; r < 4; r++) acc[i][j][r] = 0.f;

    const int nchunks = Kd >> 6;
    uint4 a_ld[AIT], b_ld[BIT];

    auto ldg_chunk = [&](int c) {
        const int k0 = c << 6;
#pragma unroll
        for (int it = 0; it < AIT; it++) {
            int idx = tid + 256 * it;
            int r = idx >> 3, q = idx & 7;
            int arow = row0 + r;
            long amap = conv_mode ? ((long)(arow >> 8) * LP_ + (arow & 255)) : (long)arow;
            a_ld[it] = *(const uint4*)(A + amap * (long)strideA + k0 + q * 8);
        }
#pragma unroll
        for (int it = 0; it < BIT; it++) {
            int idx = tid + 256 * it;
            int r = idx >> 3, q = idx & 7;
            int bn = col0 + r;
            b_ld[it] = (bn < N) ? *(const uint4*)(W + (long)bn * Kd + k0 + q * 8)
                                : make_uint4(0u, 0u, 0u, 0u);
        }
    };
    auto sts_chunk = [&](int buf) {
#pragma unroll
        for (int it = 0; it < AIT; it++) {
            int idx = tid + 256 * it;
            int r = idx >> 3, q = idx & 7;
            *(uint4*)(Abuf + buf * ABYTES + sw128(r * 128 + q * 16)) = a_ld[it];
        }
#pragma unroll
        for (int it = 0; it < BIT; it++) {
            int idx = tid + 256 * it;
            int r = idx >> 3, q = idx & 7;
            *(uint4*)(Bbuf + buf * BBYTES + sw128(r * 128 + q * 16)) = b_ld[it];
        }
    };

    ldg_chunk(0);
    sts_chunk(0);
    __syncthreads();

    const uint32_t sA0 = sb;                  // A buffers base
    const uint32_t sB0 = sb + 2 * ABYTES;     // B buffers base
    const int arow_l = (lane & 7) + ((lane >> 3) & 1) * 8;
    const int akh = (lane >> 4) & 1;
    const int brow_l = (lane & 7) + ((lane >> 4) & 1) * 8;
    const int bkh = (lane >> 3) & 1;

    for (int c = 0; c < nchunks; c++) {
        if (c + 1 < nchunks) ldg_chunk(c + 1);

        const uint32_t Ab = sA0 + (c & 1) * ABYTES;
        const uint32_t Bb = sB0 + (c & 1) * BBYTES;
#pragma unroll
        for (int ks = 0; ks < 4; ks++) {
            uint32_t a[MF][4];
#pragma unroll
            for (int mf = 0; mf < MF; mf++) {
                int row = (wm * MF + mf) * 16 + arow_l;
                ldsm_x4(a[mf][0], a[mf][1], a[mf][2], a[mf][3],
                        Ab + sw128(row * 128 + ks * 32 + akh * 16));
            }
            uint32_t b[NF][2];
#pragma unroll
            for (int ng = 0; ng < NF / 2; ng++) {
                int nrow = (wn * NF + 2 * ng) * 8 + brow_l;
                uint32_t r0, r1, r2, r3;
                ldsm_x4(r0, r1, r2, r3,
                        Bb + sw128(nrow * 128 + ks * 32 + bkh * 16));
                b[2 * ng][0] = r0; b[2 * ng][1] = r1;
                b[2 * ng + 1][0] = r2; b[2 * ng + 1][1] = r3;
            }
#pragma unroll
            for (int mf = 0; mf < MF; mf++)
#pragma unroll
                for (int nf = 0; nf < NF; nf++)
                    mma_f16(acc[mf][nf], a[mf][0], a[mf][1], a[mf][2], a[mf][3],
                            b[nf][0], b[nf][1]);
        }

        if (c + 1 < nchunks) {
            __syncthreads();
            sts_chunk((c + 1) & 1);
            __syncthreads();
        }
    }

    // ---- epilogue ----
#pragma unroll
    for (int mf = 0; mf < MF; mf++) {
        int r0 = row0 + (wm * MF + mf) * 16 + grp;
        int r1 = r0 + 8;
#pragma unroll
        for (int nf = 0; nf < NF; nf++) {
            int cb = col0 + (wn * NF + nf) * 8 + tig * 2;
            if (cb >= N) continue;
            float v0 = acc[mf][nf][0], v1 = acc[mf][nf][1];
            float v2 = acc[mf][nf][2], v3 = acc[mf][nf][3];
            if (bias) {
                float b0 = bias[cb], b1 = bias[cb + 1];
                v0 += b0; v1 += b1; v2 += b0; v3 += b1;
            }
            if (epilogue == 1) {
                v0 = (v0 > 0.f) ? v0 : 0.01f * v0;
                v1 = (v1 > 0.f) ? v1 : 0.01f * v1;
                v2 = (v2 > 0.f) ? v2 : 0.01f * v2;
                v3 = (v3 > 0.f) ? v3 : 0.01f * v3;
            }
            if (resid) {
                v0 += resid[(long)r0 * N + cb]; v1 += resid[(long)r0 * N + cb + 1];
                v2 += resid[(long)r1 * N + cb]; v3 += resid[(long)r1 * N + cb + 1];
            }
            if (C) {
                *(float2*)(C + (long)r0 * N + cb) = make_float2(v0, v1);
                *(float2*)(C + (long)r1 * N + cb) = make_float2(v2, v3);
            }
            if (C16) {
                *(__half2*)(C16 + (long)r0 * N + cb) = __floats2half2_rn(v0, v1);
                *(__half2*)(C16 + (long)r1 * N + cb) = __floats2half2_rn(v2, v3);
            }
        }
    }
}

// =====================================================================
// tensor-core attention (fp16 qkv in, fp16 ctx out)
// =====================================================================
#define ATT_SM_Q 0
#define ATT_SM_K 8192
#define ATT_SM_V 40960
#define ATT_SM_P 73728
#define ATT_SM_RED 106496
#define ATT_SMEM (106496 + 2048)

__device__ __forceinline__ uint32_t swp(int r, int c2) {
    return (uint32_t)(r * 512 + (c2 ^ ((r & 7) << 4)));
}

__global__ __launch_bounds__(256) void attn_mma(
    const __half* __restrict__ qkv, const float* __restrict__ head,
    const float* __restrict__ headT, const int* __restrict__ mask,
    const float* __restrict__ relw, int layer, __half* __restrict__ ctx)
{
    extern __shared__ char sma[];
    uint32_t sbase = smem_u32(sma);
    const int b = blockIdx.z, hh = blockIdx.y, i0 = blockIdx.x * 64;
    const int tid = threadIdx.x, warp = tid >> 5, lane = tid & 31;
    const int wm = warp >> 2, wn = warp & 3;
    const int r4 = lane >> 2, c2 = (lane & 3) * 2;

    const __half* qb = qkv + (long)b * L_ * 1536 + hh * 64;
    const __half* kb = qb + 512;
    const __half* vb = qb + 1024;

    for (int idx = tid; idx < 64 * 8; idx += 256) {
        int r = idx >> 3, q = idx & 7;
        *(uint4*)(sma + ATT_SM_Q + sw128(r * 128 + q * 16)) =
            *(const uint4*)(qb + (long)(i0 + r) * 1536 + q * 8);
    }
    for (int idx = tid; idx < 256 * 8; idx += 256) {
        int r = idx >> 3, q = idx & 7;
        *(uint4*)(sma + ATT_SM_K + sw128(r * 128 + q * 16)) =
            *(const uint4*)(kb + (long)r * 1536 + q * 8);
        *(uint4*)(sma + ATT_SM_V + sw128(r * 128 + q * 16)) =
            *(const uint4*)(vb + (long)r * 1536 + q * 8);
    }
    __syncthreads();

    float acc[2][8][4];
#pragma unroll
    for (int i = 0; i < 2; i++)
#pragma unroll
        for (int j = 0; j < 8; j++)
#pragma unroll
            for (int r = 0; r < 4; r++) acc[i][j][r] = 0.f;

#pragma unroll
    for (int kk = 0; kk < 4; kk++) {
        uint32_t a[2][4];
#pragma unroll
        for (int mf = 0; mf < 2; mf++) {
            int row = wm * 32 + mf * 16 + (lane & 7) + ((lane >> 3) & 1) * 8;
            int kh = (lane >> 4) & 1;
            ldsm_x4(a[mf][0], a[mf][1], a[mf][2], a[mf][3],
                    sbase + ATT_SM_Q + sw128(row * 128 + kk * 32 + kh * 16));
        }
        uint32_t bf[8][2];
#pragma unroll
        for (int ng = 0; ng < 4; ng++) {
            int nrow = wn * 64 + ng * 16 + (lane & 7) + ((lane >> 4) & 1) * 8;
            int kh = (lane >> 3) & 1;
            uint32_t r0, r1, r2, r3;
            ldsm_x4(r0, r1, r2, r3,
                    sbase + ATT_SM_K + sw128(nrow * 128 + kk * 32 + kh * 16));
            bf[2 * ng][0] = r0; bf[2 * ng][1] = r1;
            bf[2 * ng + 1][0] = r2; bf[2 * ng + 1][1] = r3;
        }
#pragma unroll
        for (int mf = 0; mf < 2; mf++)
#pragma unroll
            for (int nf = 0; nf < 8; nf++)
                mma_f16(acc[mf][nf], a[mf][0], a[mf][1], a[mf][2], a[mf][3],
                        bf[nf][0], bf[nf][1]);
    }

    float w0, w1;
    {
        float a0v = relw[(layer * NH_ + hh) * 2 + 0];
        float a1v = relw[(layer * NH_ + hh) * 2 + 1];
        float mv = fmaxf(a0v, a1v);
        float e0 = __expf(a0v - mv), e1 = __expf(a1v - mv);
        w0 = e0 / (e0 + e1); w1 = e1 / (e0 + e1);
    }

#pragma unroll
    for (int nf = 0; nf < 8; nf++) {
        int j = wn * 64 + nf * 8 + c2;
        int m0 = mask[b * L_ + j], m1 = mask[b * L_ + j + 1];
#pragma unroll
        for (int mf = 0; mf < 2; mf++) {
            int ia = i0 + wm * 32 + mf * 16 + r4;
            float2 hd = *(const float2*)(head + ((long)(b * L_ + ia)) * L_ + j);
            float2 ht = *(const float2*)(headT + ((long)(b * L_ + ia)) * L_ + j);
            float s0 = acc[mf][nf][0] * 0.125f + w0 * hd.x + w1 * ht.x;
            float s1 = acc[mf][nf][1] * 0.125f + w0 * hd.y + w1 * ht.y;
            acc[mf][nf][0] = m0 ? s0 : -1e30f;
            acc[mf][nf][1] = m1 ? s1 : -1e30f;
            int ib = ia + 8;
            float2 hd2 = *(const float2*)(head + ((long)(b * L_ + ib)) * L_ + j);
            float2 ht2 = *(const float2*)(headT + ((long)(b * L_ + ib)) * L_ + j);
            float s2 = acc[mf][nf][2] * 0.125f + w0 * hd2.x + w1 * ht2.x;
            float s3 = acc[mf][nf][3] * 0.125f + w0 * hd2.y + w1 * ht2.y;
            acc[mf][nf][2] = m0 ? s2 : -1e30f;
            acc[mf][nf][3] = m1 ? s3 : -1e30f;
        }
    }

    float* redm = (float*)(sma + ATT_SM_RED);
    float* reds = redm + 256;
    float mx[4];
#pragma unroll
    for (int mf = 0; mf < 2; mf++)
#pragma unroll
        for (int hf = 0; hf < 2; hf++) {
            float m = -1e30f;
#pragma unroll
            for (int nf = 0; nf < 8; nf++)
                m = fmaxf(m, fmaxf(acc[mf][nf][2 * hf], acc[mf][nf][2 * hf + 1]));
            mx[mf * 2 + hf] = m;
        }
#pragma unroll
    for (int ri = 0; ri < 4; ri++) {
        mx[ri] = fmaxf(mx[ri], __shfl_xor_sync(0xffffffffu, mx[ri], 1));
        mx[ri] = fmaxf(mx[ri], __shfl_xor_sync(0xffffffffu, mx[ri], 2));
    }
    if ((lane & 3) == 0) {
#pragma unroll
        for (int mf = 0; mf < 2; mf++)
#pragma unroll
            for (int hf = 0; hf < 2; hf++)
                redm[wn * 64 + wm * 32 + mf * 16 + hf * 8 + r4] = mx[mf * 2 + hf];
    }
    __syncthreads();
    float MX[4];
#pragma unroll
    for (int mf = 0; mf < 2; mf++)
#pragma unroll
        for (int hf = 0; hf < 2; hf++) {
            int row = wm * 32 + mf * 16 + hf * 8 + r4;
            float m = redm[row];
            m = fmaxf(m, redm[64 + row]);
            m = fmaxf(m, redm[128 + row]);
            m = fmaxf(m, redm[192 + row]);
            MX[mf * 2 + hf] = m;
        }
    float sm[4] = {0.f, 0.f, 0.f, 0.f};
#pragma unroll
    for (int mf = 0; mf < 2; mf++)
#pragma unroll
        for (int nf = 0; nf < 8; nf++)
#pragma unroll
            for (int hf = 0; hf < 2; hf++) {
                float e0 = __expf(acc[mf][nf][2 * hf] - MX[mf * 2 + hf]);
                float e1 = __expf(acc[mf][nf][2 * hf + 1] - MX[mf * 2 + hf]);
                acc[mf][nf][2 * hf] = e0;
                acc[mf][nf][2 * hf + 1] = e1;
                sm[mf * 2 + hf] += e0 + e1;
            }
#pragma unroll
    for (int ri = 0; ri < 4; ri++) {
        sm[ri] += __shfl_xor_sync(0xffffffffu, sm[ri], 1);
        sm[ri] += __shfl_xor_sync(0xffffffffu, sm[ri], 2);
    }
    if ((lane & 3) == 0) {
#pragma unroll
        for (int mf = 0; mf < 2; mf++)
#pragma unroll
            for (int hf = 0; hf < 2; hf++)
                reds[wn * 64 + wm * 32 + mf * 16 + hf * 8 + r4] = sm[mf * 2 + hf];
    }
    __syncthreads();
    float inv[4];
#pragma unroll
    for (int mf = 0; mf < 2; mf++)
#pragma unroll
        for (int hf = 0; hf < 2; hf++) {
            int row = wm * 32 + mf * 16 + hf * 8 + r4;
            float t = reds[row] + reds[64 + row] + reds[128 + row] + reds[192 + row];
            inv[mf * 2 + hf] = 1.f / t;
        }

#pragma unroll
    for (int mf = 0; mf < 2; mf++)
#pragma unroll
        for (int nf = 0; nf < 8; nf++) {
            int rowa = wm * 32 + mf * 16 + r4;
            int j = wn * 64 + nf * 8 + c2;
            *(uint32_t*)(sma + ATT_SM_P + swp(rowa, j * 2)) =
                pack_h2(acc[mf][nf][0] * inv[mf * 2], acc[mf][nf][1] * inv[mf * 2]);
            *(uint32_t*)(sma + ATT_SM_P + swp(rowa + 8, j * 2)) =
                pack_h2(acc[mf][nf][2] * inv[mf * 2 + 1], acc[mf][nf][3] * inv[mf * 2 + 1]);
        }
    __syncthreads();

    float oacc[2][2][4];
#pragma unroll
    for (int i = 0; i < 2; i++)
#pragma unroll
        for (int j = 0; j < 2; j++)
#pragma unroll
            for (int r = 0; r < 4; r++) oacc[i][j][r] = 0.f;

#pragma unroll
    for (int kk = 0; kk < 16; kk++) {
        uint32_t a[2][4];
#pragma unroll
        for (int mf = 0; mf < 2; mf++) {
            int row = wm * 32 + mf * 16 + (lane & 7) + ((lane >> 3) & 1) * 8;
            int kh = (lane >> 4) & 1;
            ldsm_x4(a[mf][0], a[mf][1], a[mf][2], a[mf][3],
                    sbase + ATT_SM_P + swp(row, kk * 32 + kh * 16));
        }
        uint32_t bf[2][2];
        {
            int kvrow = kk * 16 + (lane & 7) + ((lane >> 3) & 1) * 8;
            int nb = wn * 16 + ((lane >> 4) & 1) * 8;
            uint32_t r0, r1, r2, r3;
            ldsm_x4_t(r0, r1, r2, r3,
                      sbase + ATT_SM_V + sw128(kvrow * 128 + nb * 2));
            bf[0][0] = r0; bf[0][1] = r1; bf[1][0] = r2; bf[1][1] = r3;
        }
#pragma unroll
        for (int mf = 0; mf < 2; mf++)
#pragma unroll
            for (int nf = 0; nf < 2; nf++)
                mma_f16(oacc[mf][nf], a[mf][0], a[mf][1], a[mf][2], a[mf][3],
                        bf[nf][0], bf[nf][1]);
    }

#pragma unroll
    for (int mf = 0; mf < 2; mf++)
#pragma unroll
        for (int nf = 0; nf < 2; nf++) {
            int row = i0 + wm * 32 + mf * 16 + r4;
            int d = wn * 16 + nf * 8 + c2;
            __half* dst = ctx + ((long)(b * L_) + row) * H_ + hh * 64 + d;
            *(__half2*)dst = __floats2half2_rn(oacc[mf][nf][0], oacc[mf][nf][1]);
            *(__half2*)(dst + 8 * H_) = __floats2half2_rn(oacc[mf][nf][2], oacc[mf][nf][3]);
        }
}

// ---------------- embed + mask ----------------
__global__ void embed_kernel(const int* __restrict__ x, const float* __restrict__ emb,
                             float* __restrict__ h, int* __restrict__ mask) {
    int r = blockIdx.x;
    int tok = x[r];
    if (threadIdx.x == 0) mask[r] = (tok != 0) ? 1 : 0;
    const float* e = emb + (long)tok * H_;
    float* o = h + (long)r * H_;
    o[threadIdx.x]       = e[threadIdx.x];
    o[threadIdx.x + 256] = e[threadIdx.x + 256];
}

// ---------------- masked zero-padded fp16 copy for conv ----------------
__global__ void pad_kernel16(const float* __restrict__ h, const int* __restrict__ mask,
                             __half* __restrict__ hpad) {
    int b = blockIdx.x / LP_;
    int lp = blockIdx.x % LP_;
    int l = lp - 4;
    bool valid = (l >= 0 && l < L_) && (mask[b * L_ + l] != 0);
    __half2* dst = (__half2*)(hpad + (long)blockIdx.x * H_);
    const float2* src = (const float2*)(h + (long)(b * L_ + l) * H_);
    int c = threadIdx.x;
    float2 v = valid ? src[c] : make_float2(0.f, 0.f);
    dst[c] = __floats2half2_rn(v.x, v.y);
}

// ---------------- layernorm: fp32 in, optional fp32 out + fp16 out ----------------
__device__ __forceinline__ float block_sum_8w(float v, float* red) {
    int lane = threadIdx.x & 31, w = threadIdx.x >> 5;
#pragma unroll
    for (int o = 16; o; o >>= 1) v += __shfl_xor_sync(0xffffffffu, v, o);
    if (lane == 0) red[w] = v;
    __syncthreads();
    float t = (lane < 8) ? red[lane] : 0.f;
#pragma unroll
    for (int o = 4; o; o >>= 1) t += __shfl_xor_sync(0xffffffffu, t, o);
    return __shfl_sync(0xffffffffu, t, 0);
}

__global__ void ln_kernel(const float* __restrict__ in, float* __restrict__ out,
                          __half* __restrict__ out16,
                          const float* __restrict__ s, const float* __restrict__ b,
                          int do_tanh) {
    __shared__ float red[32];
    long r = blockIdx.x;
    const float* x = in + r * H_;
    float v0 = x[threadIdx.x];
    float v1 = x[threadIdx.x + 256];
    float sum = block_sum_8w(v0 + v1, red);
    float m = sum * (1.f / 512.f);
    float d0 = v0 - m, d1 = v1 - m;
    __syncthreads();
    float var = block_sum_8w(d0 * d0 + d1 * d1, red) * (1.f / 512.f);
    float inv = rsqrtf(var + 1e-5f);
    float y0 = d0 * inv, y1 = d1 * inv;
    if (s) {
        y0 = y0 * s[threadIdx.x] + b[threadIdx.x];
        y1 = y1 * s[threadIdx.x + 256] + b[threadIdx.x + 256];
    }
    if (do_tanh) { y0 = tanhf(y0); y1 = tanhf(y1); }
    if (out) {
        float* o = out + r * H_;
        o[threadIdx.x] = y0;
        o[threadIdx.x + 256] = y1;
    }
    if (out16) {
        __half* o = out16 + r * H_;
        o[threadIdx.x] = __float2half(y0);
        o[threadIdx.x + 256] = __float2half(y1);
    }
}

// ---------------- parse softmax ----------------
__global__ void softmax_head_kernel(float* __restrict__ head, const int* __restrict__ mask) {
    __shared__ float red[32];
    int bi = blockIdx.x;
    int b = bi >> 8, i = bi & 255;
    float* row = head + (long)bi * L_;
    int j = threadIdx.x;
    float v = (mask[b * L_ + j] != 0) ? row[j] * (1.f / 512.f) : -INFINITY;

    int lane = threadIdx.x & 31, w = threadIdx.x >> 5;
    float m = v;
#pragma unroll
    for (int o = 16; o; o >>= 1) m = fmaxf(m, __shfl_xor_sync(0xffffffffu, m, o));
    if (lane == 0) red[w] = m;
    __syncthreads();
    float t = (lane < 8) ? red[lane] : -INFINITY;
#pragma unroll
    for (int o = 4; o; o >>= 1) t = fmaxf(t, __shfl_xor_sync(0xffffffffu, t, o));
    m = __shfl_sync(0xffffffffu, t, 0);
    __syncthreads();

    float e = (v == -INFINITY) ? 0.f : __expf(v - m);
    float sum = block_sum_8w(e, red);
    float p = (sum > 0.f) ? e / sum : 0.f;
    if (j == i) p = 0.f;
    row[j] = p;
}

// ---------------- head transpose ----------------
__global__ void transpose_kernel(const float* __restrict__ head, float* __restrict__ headT) {
    __shared__ float t[32][33];
    int b = blockIdx.z;
    int i0 = blockIdx.y * 32, j0 = blockIdx.x * 32;
    const float* src = head + (long)b * L_ * L_;
    t[threadIdx.y][threadIdx.x] = src[(long)(i0 + threadIdx.y) * L_ + j0 + threadIdx.x];
    __syncthreads();
    headT[(long)b * L_ * L_ + (long)(j0 + threadIdx.y) * L_ + i0 + threadIdx.x] =
        t[threadIdx.x][threadIdx.y];
}

// ---------------- host orchestration ----------------
#define GSM_SMALL (2 * (128 * 128 + 64 * 128))     // 49152
#define GSM_BIG   (2 * (128 * 128 + 128 * 128))    // 65536

static inline void launch_h(const __half* A, const __half* W, const float* bias,
                            const float* resid, float* C, __half* C16,
                            int M, int N, int Kd, int epilogue,
                            int conv_mode = 0, int strideA = -1,
                            int batch = 1, long sA = 0, long sB = 0, long sC = 0) {
    if (strideA < 0) strideA = Kd;
    if (N <= 512) {
        dim3 g((N + 63) / 64, M / 128, batch);
        gemm_h<4, 2, 2, 4><<<g, 256, GSM_SMALL>>>(A, W, bias, resid, C, C16,
                                                  M, N, Kd, strideA, sA, sB, sC,
                                                  epilogue, conv_mode);
    } else {
        dim3 g((N + 127) / 128, M / 128, batch);
        gemm_h<2, 4, 4, 4><<<g, 256, GSM_BIG>>>(A, W, bias, resid, C, C16,
                                                M, N, Kd, strideA, sA, sB, sC,
                                                epilogue, conv_mode);
    }
}

static inline void cvt(const float* src, __half* dst, long n) {
    int n4 = (int)(n / 4);
    cvt_f2h<<<(n4 + 255) / 256, 256>>>(src, dst, n4);
}

extern "C" void kernel_launch(void* const* d_in, const int* in_sizes, int n_in,
                              void* d_out, int out_size) {
    const int*   x        = (const int*)d_in[0];
    const float* emb      = (const float*)d_in[2];
    const float* conv_w   = (const float*)d_in[3];
    const float* conv_b   = (const float*)d_in[4];
    const float* parent_w = (const float*)d_in[5];
    const float* parent_b = (const float*)d_in[6];
    const float* child_w  = (const float*)d_in[7];
    const float* child_b  = (const float*)d_in[8];
    const float* rel_w    = (const float*)d_in[9];
    const float* qkv_w    = (const float*)d_in[10];
    const float* qkv_b    = (const float*)d_in[11];
    const float* out_w    = (const float*)d_in[12];
    const float* out_b    = (const float*)d_in[13];
    const float* ln1_s    = (const float*)d_in[14];
    const float* ln1_b    = (const float*)d_in[15];
    const float* ln2_s    = (const float*)d_in[16];
    const float* ln2_b    = (const float*)d_in[17];
    const float* ff1_w    = (const float*)d_in[18];
    const float* ff1_b    = (const float*)d_in[19];
    const float* ff2_w    = (const float*)d_in[20];
    const float* ff2_b    = (const float*)d_in[21];
    const float* norm_s   = (const float*)d_in[22];
    const float* norm_b   = (const float*)d_in[23];
    const float* out_bias = (const float*)d_in[24];
    float* out = (float*)d_out;

    void *p;
    cudaGetSymbolAddress(&p, g_h);       float*  h      = (float*)p;
    cudaGetSymbolAddress(&p, g_tmp);     float*  tmp    = (float*)p;
    cudaGetSymbolAddress(&p, g_head);    float*  head   = (float*)p;
    cudaGetSymbolAddress(&p, g_headT);   float*  headT  = (float*)p;
    cudaGetSymbolAddress(&p, g_mask);    int*    mask   = (int*)p;
    cudaGetSymbolAddress(&p, g_h16);     __half* h16    = (__half*)p;
    cudaGetSymbolAddress(&p, g_hn16);    __half* hn16   = (__half*)p;
    cudaGetSymbolAddress(&p, g_hpad16);  __half* hpad16 = (__half*)p;
    cudaGetSymbolAddress(&p, g_par16);   __half* par16  = (__half*)p;
    cudaGetSymbolAddress(&p, g_chi16);   __half* chi16  = (__half*)p;
    cudaGetSymbolAddress(&p, g_qkv16);   __half* qkv16  = (__half*)p;
    cudaGetSymbolAddress(&p, g_ctx16);   __half* ctx16  = (__half*)p;
    cudaGetSymbolAddress(&p, g_ff16);    __half* ff16   = (__half*)p;
    cudaGetSymbolAddress(&p, g_convT16); __half* convT16 = (__half*)p;
    cudaGetSymbolAddress(&p, g_qkvw16);  __half* qkvw16 = (__half*)p;
    cudaGetSymbolAddress(&p, g_outw16);  __half* outw16 = (__half*)p;
    cudaGetSymbolAddress(&p, g_ff1w16);  __half* ff1w16 = (__half*)p;
    cudaGetSymbolAddress(&p, g_ff2w16);  __half* ff2w16 = (__half*)p;
    cudaGetSymbolAddress(&p, g_parw16);  __half* parw16 = (__half*)p;
    cudaGetSymbolAddress(&p, g_chiw16);  __half* chiw16 = (__half*)p;
    cudaGetSymbolAddress(&p, g_emb16);   __half* emb16  = (__half*)p;

    cudaFuncSetAttribute(attn_mma, cudaFuncAttributeMaxDynamicSharedMemorySize, ATT_SMEM);
    cudaFuncSetAttribute(gemm_h<4, 2, 2, 4>,
                         cudaFuncAttributeMaxDynamicSharedMemorySize, GSM_SMALL);
    cudaFuncSetAttribute(gemm_h<2, 4, 4, 4>,
                         cudaFuncAttributeMaxDynamicSharedMemorySize, GSM_BIG);

    // ---- weight conversions ----
    convw_transpose16<<<dim3(16, 16, P_ * KW_), dim3(32, 32)>>>(conv_w, convT16);
    cvt(qkv_w, qkvw16, (long)NL_ * 3 * H_ * H_);
    cvt(out_w, outw16, (long)NL_ * H_ * H_);
    cvt(ff1_w, ff1w16, (long)NL_ * DFF_ * H_);
    cvt(ff2_w, ff2w16, (long)NL_ * H_ * DFF_);
    cvt(parent_w, parw16, (long)H_ * H_);
    cvt(child_w, chiw16, (long)H_ * H_);
    cvt(emb, emb16, (long)NTOK_ * H_);

    // ---- embedding + mask ----
    embed_kernel<<<BL_, 256>>>(x, emb, h, mask);

    // ---- parser: pad(fp16) -> conv GEMM -> LN+tanh ----
    for (int pl = 0; pl < P_; pl++) {
        pad_kernel16<<<B_ * LP_, 256>>>(h, mask, hpad16);
        launch_h(hpad16, convT16 + (long)pl * H_ * KW_ * H_, conv_b + pl * H_,
                 nullptr, tmp, nullptr, BL_, H_, KW_ * H_, 0,
                 /*conv_mode=*/1, /*strideA=*/H_);
        ln_kernel<<<BL_, 256>>>(tmp, h, h16, nullptr, nullptr, 1);
    }

    // ---- parent / child (fp16 outputs) ----
    launch_h(h16, parw16, parent_b, nullptr, nullptr, par16, BL_, H_, H_, 0);
    launch_h(h16, chiw16, child_b, nullptr, nullptr, chi16, BL_, H_, H_, 0);

    // ---- parse logits + softmax + transpose ----
    launch_h(chi16, par16, nullptr, nullptr, head, nullptr, L_, L_, H_, 0, 0, -1,
             B_, (long)L_ * H_, (long)L_ * H_, (long)L_ * L_);
    softmax_head_kernel<<<BL_, 256>>>(head, mask);
    transpose_kernel<<<dim3(8, 8, B_), dim3(32, 32)>>>(head, headT);

    // ---- transformer ----
    embed_kernel<<<BL_, 256>>>(x, emb, h, mask);
    for (int i = 0; i < NL_; i++) {
        ln_kernel<<<BL_, 256>>>(h, nullptr, hn16, ln1_s + i * H_, ln1_b + i * H_, 0);
        launch_h(hn16, qkvw16 + (long)i * 3 * H_ * H_, qkv_b + i * 3 * H_,
                 nullptr, nullptr, qkv16, BL_, 3 * H_, H_, 0);
        attn_mma<<<dim3(4, NH_, B_), 256, ATT_SMEM>>>(qkv16, head, headT, mask,
                                                      rel_w, i, ctx16);
        launch_h(ctx16, outw16 + (long)i * H_ * H_, out_b + i * H_, h, h, nullptr,
                 BL_, H_, H_, 0);
        ln_kernel<<<BL_, 256>>>(h, nullptr, hn16, ln2_s + i * H_, ln2_b + i * H_, 0);
        launch_h(hn16, ff1w16 + (long)i * DFF_ * H_, ff1_b + i * DFF_,
                 nullptr, nullptr, ff16, BL_, DFF_, H_, 1);
        launch_h(ff16, ff2w16 + (long)i * H_ * DFF_, ff2_b + i * H_, h, h, nullptr,
                 BL_, H_, DFF_, 0);
    }

    // ---- final LN + tied output ----
    ln_kernel<<<BL_, 256>>>(h, nullptr, hn16, norm_s, norm_b, 0);
    launch_h(hn16, emb16, out_bias, nullptr, out, nullptr, BL_, NTOK_, H_, 0);
}

// round 7
// speedup vs baseline: 8.0730x; 1.2067x over previous
#include <cuda_runtime.h>
#include <cuda_fp16.h>
#include <math.h>
#include <stdint.h>

#define B_ 16
#define L_ 256
#define H_ 512
#define NH_ 8
#define DH_ 64
#define NL_ 6
#define NTOK_ 10000
#define P_ 4
#define KW_ 9
#define DFF_ 2048
#define BL_ (B_ * L_)

// ---------------- device scratch (fp32) ----------------
__device__ float g_h[BL_ * H_];
__device__ float g_tmp[BL_ * H_];
__device__ float g_head[B_ * L_ * L_];
__device__ float g_headT[B_ * L_ * L_];
__device__ int   g_mask[BL_];
// ---------------- device scratch (fp16) ----------------
__device__ __half g_h16[BL_ * H_];
__device__ __half g_hn16[BL_ * H_];
__device__ __half g_par16[BL_ * H_];
__device__ __half g_chi16[BL_ * H_];
__device__ __half g_qkv16[BL_ * 3 * H_];
__device__ __half g_ctx16[BL_ * H_];
__device__ __half g_ff16[BL_ * DFF_];
// fp16 weights
__device__ __half g_convT16[P_ * H_ * KW_ * H_];
__device__ __half g_qkvw16[NL_ * 3 * H_ * H_];
__device__ __half g_outw16[NL_ * H_ * H_];
__device__ __half g_ff1w16[NL_ * DFF_ * H_];
__device__ __half g_ff2w16[NL_ * H_ * DFF_];
__device__ __half g_parw16[H_ * H_];
__device__ __half g_chiw16[H_ * H_];
__device__ __half g_emb16[NTOK_ * H_];

// ================= helpers =================
__device__ __forceinline__ uint32_t pack_h2(float x, float y) {
    __half2 h = __floats2half2_rn(x, y);
    return *reinterpret_cast<uint32_t*>(&h);
}
__device__ __forceinline__ uint32_t smem_u32(const void* p) {
    uint32_t a;
    asm("{ .reg .u64 t; cvta.to.shared.u64 t, %1; cvt.u32.u64 %0, t; }" : "=r"(a) : "l"(p));
    return a;
}
__device__ __forceinline__ uint32_t sw128(uint32_t x) { return x ^ ((x >> 3) & 0x70); }

__device__ __forceinline__ void mma_f16(float c[4], uint32_t a0, uint32_t a1,
                                        uint32_t a2, uint32_t a3,
                                        uint32_t b0, uint32_t b1) {
    asm volatile(
        "mma.sync.aligned.m16n8k16.row.col.f32.f16.f16.f32 "
        "{%0,%1,%2,%3}, {%4,%5,%6,%7}, {%8,%9}, {%0,%1,%2,%3};\n"
        : "+f"(c[0]), "+f"(c[1]), "+f"(c[2]), "+f"(c[3])
        : "r"(a0), "r"(a1), "r"(a2), "r"(a3), "r"(b0), "r"(b1));
}
__device__ __forceinline__ void ldsm_x4(uint32_t& r0, uint32_t& r1, uint32_t& r2,
                                        uint32_t& r3, uint32_t addr) {
    asm volatile("ldmatrix.sync.aligned.m8n8.x4.shared.b16 {%0,%1,%2,%3}, [%4];"
                 : "=r"(r0), "=r"(r1), "=r"(r2), "=r"(r3) : "r"(addr));
}
__device__ __forceinline__ void ldsm_x4_t(uint32_t& r0, uint32_t& r1, uint32_t& r2,
                                          uint32_t& r3, uint32_t addr) {
    asm volatile("ldmatrix.sync.aligned.m8n8.x4.trans.shared.b16 {%0,%1,%2,%3}, [%4];"
                 : "=r"(r0), "=r"(r1), "=r"(r2), "=r"(r3) : "r"(addr));
}
__device__ __forceinline__ void cp16(uint32_t dst, const __half* src, int sz) {
    asm volatile("cp.async.cg.shared.global [%0], [%1], 16, %2;"
                 :: "r"(dst), "l"(__cvta_generic_to_global(src)), "r"(sz));
}

// ---------------- fp32 -> fp16 convert ----------------
__global__ void cvt_f2h(const float* __restrict__ src, __half* __restrict__ dst, int n4) {
    int i = blockIdx.x * 256 + threadIdx.x;
    if (i < n4) {
        float4 v = *(const float4*)(src + i * 4);
        *(uint2*)(dst + i * 4) = make_uint2(pack_h2(v.x, v.y), pack_h2(v.z, v.w));
    }
}

// conv weights: w[p][k][ci][co] -> wt16[p][co][k*H+ci]
__global__ void convw_transpose16(const float* __restrict__ w, __half* __restrict__ wt) {
    __shared__ float t[32][33];
    int pk = blockIdx.z;
    int p = pk / KW_, k = pk % KW_;
    int ci0 = blockIdx.y * 32, co0 = blockIdx.x * 32;
    t[threadIdx.y][threadIdx.x] =
        w[((long)pk * H_ + ci0 + threadIdx.y) * H_ + co0 + threadIdx.x];
    __syncthreads();
    wt[((long)p * H_ + co0 + threadIdx.y) * (KW_ * H_) + k * H_ + ci0 + threadIdx.x] =
        __float2half(t[threadIdx.x][threadIdx.y]);
}

// =====================================================================
// fp16 GEMM: cp.async 3-stage pipeline, SW128 rows + ldmatrix.
// C = A(M,K) @ W(N,K)^T (+bias)(+leaky)(+resid)
// conv_mode: A row m -> h16[(m>>8)*256 + (m&255) + seq - 4, :] with mask/bounds,
//            flat K = 9*512 (seq = chunk>>3).
// =====================================================================
#define NSTAGE 3

template <int WM, int WN, int MF, int NF>
__global__ __launch_bounds__(256) void gemm_h(
    const __half* __restrict__ A, const __half* __restrict__ W,
    const float* __restrict__ bias, const float* __restrict__ resid,
    float* __restrict__ C, __half* __restrict__ C16,
    const int* __restrict__ cmask,
    int M, int N, int Kd, int strideA,
    long sA, long sB, long sC,
    int epilogue, int conv_mode)
{
    constexpr int BM = WM * MF * 16;
    constexpr int BN = WN * NF * 8;
    constexpr int ABYTES = BM * 128;
    constexpr int BBYTES = BN * 128;
    constexpr int STAGEB = ABYTES + BBYTES;
    constexpr int AIT = BM * 8 / 256;
    constexpr int BIT = BN * 8 / 256;

    extern __shared__ char smem[];
    uint32_t sb = smem_u32(smem);

    int bz = blockIdx.z;
    A += (long)bz * sA;
    W += (long)bz * sB;
    if (C) C += (long)bz * sC;
    if (C16) C16 += (long)bz * sC;
    if (resid) resid += (long)bz * sC;

    const int tid = threadIdx.x;
    const int warp = tid >> 5, lane = tid & 31;
    const int wm = warp / WN;
    const int wn = warp % WN;
    const int grp = lane >> 2, tig = lane & 3;
    const int row0 = blockIdx.y * BM;
    const int col0 = blockIdx.x * BN;

    float acc[MF][NF][4];
#pragma unroll
    for (int i = 0; i < MF; i++)
#pragma unroll
        for (int j = 0; j < NF; j++)
#pragma unroll
            for (int r = 0; r < 4; r++) acc[i][j][r] = 0.f;

    const int nchunks = Kd >> 6;

    auto issue = [&](int c) {
        if (c < nchunks) {
            uint32_t abase = sb + (c % NSTAGE) * STAGEB;
            uint32_t bbase = abase + ABYTES;
            const int k0 = c << 6;
#pragma unroll
            for (int it = 0; it < AIT; it++) {
                int idx = tid + 256 * it;
                int r = idx >> 3, q = idx & 7;
                int arow = row0 + r;
                const __half* src;
                int sz = 16;
                if (conv_mode) {
                    int bb = arow >> 8;
                    int ll = (arow & 255) + (c >> 3) - 4;
                    int lc = min(max(ll, 0), 255);
                    bool av = (ll >= 0) && (ll < 256) && (cmask[bb * 256 + lc] != 0);
                    src = A + ((long)(bb * 256 + lc) * 512) + (k0 & 511) + q * 8;
                    sz = av ? 16 : 0;
                } else {
                    src = A + (long)arow * strideA + k0 + q * 8;
                }
                cp16(abase + sw128(r * 128 + q * 16), src, sz);
            }
#pragma unroll
            for (int it = 0; it < BIT; it++) {
                int idx = tid + 256 * it;
                int r = idx >> 3, q = idx & 7;
                int bn = col0 + r;
                int bc = min(bn, N - 1);
                int sz = (bn < N) ? 16 : 0;
                cp16(bbase + sw128(r * 128 + q * 16), W + (long)bc * Kd + k0 + q * 8, sz);
            }
        }
        asm volatile("cp.async.commit_group;" ::: "memory");
    };

#pragma unroll
    for (int s = 0; s < NSTAGE - 1; s++) issue(s);

    const int arow_l = (lane & 7) + ((lane >> 3) & 1) * 8;
    const int akh = (lane >> 4) & 1;
    const int brow_l = (lane & 7) + ((lane >> 4) & 1) * 8;
    const int bkh = (lane >> 3) & 1;

    for (int c = 0; c < nchunks; c++) {
        asm volatile("cp.async.wait_group %0;" :: "n"(NSTAGE - 2) : "memory");
        __syncthreads();
        issue(c + NSTAGE - 1);

        const uint32_t Ab = sb + (c % NSTAGE) * STAGEB;
        const uint32_t Bb = Ab + ABYTES;
#pragma unroll
        for (int ks = 0; ks < 4; ks++) {
            uint32_t a[MF][4];
#pragma unroll
            for (int mf = 0; mf < MF; mf++) {
                int row = (wm * MF + mf) * 16 + arow_l;
                ldsm_x4(a[mf][0], a[mf][1], a[mf][2], a[mf][3],
                        Ab + sw128(row * 128 + ks * 32 + akh * 16));
            }
            uint32_t b[NF][2];
#pragma unroll
            for (int ng = 0; ng < NF / 2; ng++) {
                int nrow = (wn * NF + 2 * ng) * 8 + brow_l;
                uint32_t r0, r1, r2, r3;
                ldsm_x4(r0, r1, r2, r3,
                        Bb + sw128(nrow * 128 + ks * 32 + bkh * 16));
                b[2 * ng][0] = r0; b[2 * ng][1] = r1;
                b[2 * ng + 1][0] = r2; b[2 * ng + 1][1] = r3;
            }
#pragma unroll
            for (int mf = 0; mf < MF; mf++)
#pragma unroll
                for (int nf = 0; nf < NF; nf++)
                    mma_f16(acc[mf][nf], a[mf][0], a[mf][1], a[mf][2], a[mf][3],
                            b[nf][0], b[nf][1]);
        }
    }

    // ---- epilogue ----
#pragma unroll
    for (int mf = 0; mf < MF; mf++) {
        int r0 = row0 + (wm * MF + mf) * 16 + grp;
        int r1 = r0 + 8;
#pragma unroll
        for (int nf = 0; nf < NF; nf++) {
            int cb = col0 + (wn * NF + nf) * 8 + tig * 2;
            if (cb >= N) continue;
            float v0 = acc[mf][nf][0], v1 = acc[mf][nf][1];
            float v2 = acc[mf][nf][2], v3 = acc[mf][nf][3];
            if (bias) {
                float b0 = bias[cb], b1 = bias[cb + 1];
                v0 += b0; v1 += b1; v2 += b0; v3 += b1;
            }
            if (epilogue == 1) {
                v0 = (v0 > 0.f) ? v0 : 0.01f * v0;
                v1 = (v1 > 0.f) ? v1 : 0.01f * v1;
                v2 = (v2 > 0.f) ? v2 : 0.01f * v2;
                v3 = (v3 > 0.f) ? v3 : 0.01f * v3;
            }
            if (resid) {
                v0 += resid[(long)r0 * N + cb]; v1 += resid[(long)r0 * N + cb + 1];
                v2 += resid[(long)r1 * N + cb]; v3 += resid[(long)r1 * N + cb + 1];
            }
            if (C) {
                *(float2*)(C + (long)r0 * N + cb) = make_float2(v0, v1);
                *(float2*)(C + (long)r1 * N + cb) = make_float2(v2, v3);
            }
            if (C16) {
                *(__half2*)(C16 + (long)r0 * N + cb) = __floats2half2_rn(v0, v1);
                *(__half2*)(C16 + (long)r1 * N + cb) = __floats2half2_rn(v2, v3);
            }
        }
    }
}

// =====================================================================
// tensor-core attention (fp16 qkv in, fp16 ctx out)
// =====================================================================
#define ATT_SM_Q 0
#define ATT_SM_K 8192
#define ATT_SM_V 40960
#define ATT_SM_P 73728
#define ATT_SM_RED 106496
#define ATT_SMEM (106496 + 2048)

__device__ __forceinline__ uint32_t swp(int r, int c2) {
    return (uint32_t)(r * 512 + (c2 ^ ((r & 7) << 4)));
}

__global__ __launch_bounds__(256) void attn_mma(
    const __half* __restrict__ qkv, const float* __restrict__ head,
    const float* __restrict__ headT, const int* __restrict__ mask,
    const float* __restrict__ relw, int layer, __half* __restrict__ ctx)
{
    extern __shared__ char sma[];
    uint32_t sbase = smem_u32(sma);
    const int b = blockIdx.z, hh = blockIdx.y, i0 = blockIdx.x * 64;
    const int tid = threadIdx.x, warp = tid >> 5, lane = tid & 31;
    const int wm = warp >> 2, wn = warp & 3;
    const int r4 = lane >> 2, c2 = (lane & 3) * 2;

    const __half* qb = qkv + (long)b * L_ * 1536 + hh * 64;
    const __half* kb = qb + 512;
    const __half* vb = qb + 1024;

    for (int idx = tid; idx < 64 * 8; idx += 256) {
        int r = idx >> 3, q = idx & 7;
        cp16(sbase + ATT_SM_Q + sw128(r * 128 + q * 16),
             qb + (long)(i0 + r) * 1536 + q * 8, 16);
    }
    for (int idx = tid; idx < 256 * 8; idx += 256) {
        int r = idx >> 3, q = idx & 7;
        cp16(sbase + ATT_SM_K + sw128(r * 128 + q * 16), kb + (long)r * 1536 + q * 8, 16);
        cp16(sbase + ATT_SM_V + sw128(r * 128 + q * 16), vb + (long)r * 1536 + q * 8, 16);
    }
    asm volatile("cp.async.commit_group;" ::: "memory");
    asm volatile("cp.async.wait_group 0;" ::: "memory");
    __syncthreads();

    float acc[2][8][4];
#pragma unroll
    for (int i = 0; i < 2; i++)
#pragma unroll
        for (int j = 0; j < 8; j++)
#pragma unroll
            for (int r = 0; r < 4; r++) acc[i][j][r] = 0.f;

#pragma unroll
    for (int kk = 0; kk < 4; kk++) {
        uint32_t a[2][4];
#pragma unroll
        for (int mf = 0; mf < 2; mf++) {
            int row = wm * 32 + mf * 16 + (lane & 7) + ((lane >> 3) & 1) * 8;
            int kh = (lane >> 4) & 1;
            ldsm_x4(a[mf][0], a[mf][1], a[mf][2], a[mf][3],
                    sbase + ATT_SM_Q + sw128(row * 128 + kk * 32 + kh * 16));
        }
        uint32_t bf[8][2];
#pragma unroll
        for (int ng = 0; ng < 4; ng++) {
            int nrow = wn * 64 + ng * 16 + (lane & 7) + ((lane >> 4) & 1) * 8;
            int kh = (lane >> 3) & 1;
            uint32_t r0, r1, r2, r3;
            ldsm_x4(r0, r1, r2, r3,
                    sbase + ATT_SM_K + sw128(nrow * 128 + kk * 32 + kh * 16));
            bf[2 * ng][0] = r0; bf[2 * ng][1] = r1;
            bf[2 * ng + 1][0] = r2; bf[2 * ng + 1][1] = r3;
        }
#pragma unroll
        for (int mf = 0; mf < 2; mf++)
#pragma unroll
            for (int nf = 0; nf < 8; nf++)
                mma_f16(acc[mf][nf], a[mf][0], a[mf][1], a[mf][2], a[mf][3],
                        bf[nf][0], bf[nf][1]);
    }

    float w0, w1;
    {
        float a0v = relw[(layer * NH_ + hh) * 2 + 0];
        float a1v = relw[(layer * NH_ + hh) * 2 + 1];
        float mv = fmaxf(a0v, a1v);
        float e0 = __expf(a0v - mv), e1 = __expf(a1v - mv);
        w0 = e0 / (e0 + e1); w1 = e1 / (e0 + e1);
    }

#pragma unroll
    for (int nf = 0; nf < 8; nf++) {
        int j = wn * 64 + nf * 8 + c2;
        int m0 = mask[b * L_ + j], m1 = mask[b * L_ + j + 1];
#pragma unroll
        for (int mf = 0; mf < 2; mf++) {
            int ia = i0 + wm * 32 + mf * 16 + r4;
            float2 hd = *(const float2*)(head + ((long)(b * L_ + ia)) * L_ + j);
            float2 ht = *(const float2*)(headT + ((long)(b * L_ + ia)) * L_ + j);
            float s0 = acc[mf][nf][0] * 0.125f + w0 * hd.x + w1 * ht.x;
            float s1 = acc[mf][nf][1] * 0.125f + w0 * hd.y + w1 * ht.y;
            acc[mf][nf][0] = m0 ? s0 : -1e30f;
            acc[mf][nf][1] = m1 ? s1 : -1e30f;
            int ib = ia + 8;
            float2 hd2 = *(const float2*)(head + ((long)(b * L_ + ib)) * L_ + j);
            float2 ht2 = *(const float2*)(headT + ((long)(b * L_ + ib)) * L_ + j);
            float s2 = acc[mf][nf][2] * 0.125f + w0 * hd2.x + w1 * ht2.x;
            float s3 = acc[mf][nf][3] * 0.125f + w0 * hd2.y + w1 * ht2.y;
            acc[mf][nf][2] = m0 ? s2 : -1e30f;
            acc[mf][nf][3] = m1 ? s3 : -1e30f;
        }
    }

    float* redm = (float*)(sma + ATT_SM_RED);
    float* reds = redm + 256;
    float mx[4];
#pragma unroll
    for (int mf = 0; mf < 2; mf++)
#pragma unroll
        for (int hf = 0; hf < 2; hf++) {
            float m = -1e30f;
#pragma unroll
            for (int nf = 0; nf < 8; nf++)
                m = fmaxf(m, fmaxf(acc[mf][nf][2 * hf], acc[mf][nf][2 * hf + 1]));
            mx[mf * 2 + hf] = m;
        }
#pragma unroll
    for (int ri = 0; ri < 4; ri++) {
        mx[ri] = fmaxf(mx[ri], __shfl_xor_sync(0xffffffffu, mx[ri], 1));
        mx[ri] = fmaxf(mx[ri], __shfl_xor_sync(0xffffffffu, mx[ri], 2));
    }
    if ((lane & 3) == 0) {
#pragma unroll
        for (int mf = 0; mf < 2; mf++)
#pragma unroll
            for (int hf = 0; hf < 2; hf++)
                redm[wn * 64 + wm * 32 + mf * 16 + hf * 8 + r4] = mx[mf * 2 + hf];
    }
    __syncthreads();
    float MX[4];
#pragma unroll
    for (int mf = 0; mf < 2; mf++)
#pragma unroll
        for (int hf = 0; hf < 2; hf++) {
            int row = wm * 32 + mf * 16 + hf * 8 + r4;
            float m = redm[row];
            m = fmaxf(m, redm[64 + row]);
            m = fmaxf(m, redm[128 + row]);
            m = fmaxf(m, redm[192 + row]);
            MX[mf * 2 + hf] = m;
        }
    float sm[4] = {0.f, 0.f, 0.f, 0.f};
#pragma unroll
    for (int mf = 0; mf < 2; mf++)
#pragma unroll
        for (int nf = 0; nf < 8; nf++)
#pragma unroll
            for (int hf = 0; hf < 2; hf++) {
                float e0 = __expf(acc[mf][nf][2 * hf] - MX[mf * 2 + hf]);
                float e1 = __expf(acc[mf][nf][2 * hf + 1] - MX[mf * 2 + hf]);
                acc[mf][nf][2 * hf] = e0;
                acc[mf][nf][2 * hf + 1] = e1;
                sm[mf * 2 + hf] += e0 + e1;
            }
#pragma unroll
    for (int ri = 0; ri < 4; ri++) {
        sm[ri] += __shfl_xor_sync(0xffffffffu, sm[ri], 1);
        sm[ri] += __shfl_xor_sync(0xffffffffu, sm[ri], 2);
    }
    if ((lane & 3) == 0) {
#pragma unroll
        for (int mf = 0; mf < 2; mf++)
#pragma unroll
            for (int hf = 0; hf < 2; hf++)
                reds[wn * 64 + wm * 32 + mf * 16 + hf * 8 + r4] = sm[mf * 2 + hf];
    }
    __syncthreads();
    float inv[4];
#pragma unroll
    for (int mf = 0; mf < 2; mf++)
#pragma unroll
        for (int hf = 0; hf < 2; hf++) {
            int row = wm * 32 + mf * 16 + hf * 8 + r4;
            float t = reds[row] + reds[64 + row] + reds[128 + row] + reds[192 + row];
            inv[mf * 2 + hf] = 1.f / t;
        }

#pragma unroll
    for (int mf = 0; mf < 2; mf++)
#pragma unroll
        for (int nf = 0; nf < 8; nf++) {
            int rowa = wm * 32 + mf * 16 + r4;
            int j = wn * 64 + nf * 8 + c2;
            *(uint32_t*)(sma + ATT_SM_P + swp(rowa, j * 2)) =
                pack_h2(acc[mf][nf][0] * inv[mf * 2], acc[mf][nf][1] * inv[mf * 2]);
            *(uint32_t*)(sma + ATT_SM_P + swp(rowa + 8, j * 2)) =
                pack_h2(acc[mf][nf][2] * inv[mf * 2 + 1], acc[mf][nf][3] * inv[mf * 2 + 1]);
        }
    __syncthreads();

    float oacc[2][2][4];
#pragma unroll
    for (int i = 0; i < 2; i++)
#pragma unroll
        for (int j = 0; j < 2; j++)
#pragma unroll
            for (int r = 0; r < 4; r++) oacc[i][j][r] = 0.f;

#pragma unroll
    for (int kk = 0; kk < 16; kk++) {
        uint32_t a[2][4];
#pragma unroll
        for (int mf = 0; mf < 2; mf++) {
            int row = wm * 32 + mf * 16 + (lane & 7) + ((lane >> 3) & 1) * 8;
            int kh = (lane >> 4) & 1;
            ldsm_x4(a[mf][0], a[mf][1], a[mf][2], a[mf][3],
                    sbase + ATT_SM_P + swp(row, kk * 32 + kh * 16));
        }
        uint32_t bf[2][2];
        {
            int kvrow = kk * 16 + (lane & 7) + ((lane >> 3) & 1) * 8;
            int nb = wn * 16 + ((lane >> 4) & 1) * 8;
            uint32_t r0, r1, r2, r3;
            ldsm_x4_t(r0, r1, r2, r3,
                      sbase + ATT_SM_V + sw128(kvrow * 128 + nb * 2));
            bf[0][0] = r0; bf[0][1] = r1; bf[1][0] = r2; bf[1][1] = r3;
        }
#pragma unroll
        for (int mf = 0; mf < 2; mf++)
#pragma unroll
            for (int nf = 0; nf < 2; nf++)
                mma_f16(oacc[mf][nf], a[mf][0], a[mf][1], a[mf][2], a[mf][3],
                        bf[nf][0], bf[nf][1]);
    }

#pragma unroll
    for (int mf = 0; mf < 2; mf++)
#pragma unroll
        for (int nf = 0; nf < 2; nf++) {
            int row = i0 + wm * 32 + mf * 16 + r4;
            int d = wn * 16 + nf * 8 + c2;
            __half* dst = ctx + ((long)(b * L_) + row) * H_ + hh * 64 + d;
            *(__half2*)dst = __floats2half2_rn(oacc[mf][nf][0], oacc[mf][nf][1]);
            *(__half2*)(dst + 8 * H_) = __floats2half2_rn(oacc[mf][nf][2], oacc[mf][nf][3]);
        }
}

// ---------------- embed + mask (fp32 + fp16 out) ----------------
__global__ void embed_kernel(const int* __restrict__ x, const float* __restrict__ emb,
                             float* __restrict__ h, __half* __restrict__ h16,
                             int* __restrict__ mask) {
    int r = blockIdx.x;
    int tok = x[r];
    if (threadIdx.x == 0) mask[r] = (tok != 0) ? 1 : 0;
    const float* e = emb + (long)tok * H_;
    float v0 = e[threadIdx.x];
    float v1 = e[threadIdx.x + 256];
    float* o = h + (long)r * H_;
    o[threadIdx.x] = v0;
    o[threadIdx.x + 256] = v1;
    __half* o16 = h16 + (long)r * H_;
    o16[threadIdx.x] = __float2half(v0);
    o16[threadIdx.x + 256] = __float2half(v1);
}

// ---------------- layernorm: fp32 in, optional fp32 out + fp16 out ----------------
__device__ __forceinline__ float block_sum_8w(float v, float* red) {
    int lane = threadIdx.x & 31, w = threadIdx.x >> 5;
#pragma unroll
    for (int o = 16; o; o >>= 1) v += __shfl_xor_sync(0xffffffffu, v, o);
    if (lane == 0) red[w] = v;
    __syncthreads();
    float t = (lane < 8) ? red[lane] : 0.f;
#pragma unroll
    for (int o = 4; o; o >>= 1) t += __shfl_xor_sync(0xffffffffu, t, o);
    return __shfl_sync(0xffffffffu, t, 0);
}

__global__ void ln_kernel(const float* __restrict__ in, float* __restrict__ out,
                          __half* __restrict__ out16,
                          const float* __restrict__ s, const float* __restrict__ b,
                          int do_tanh) {
    __shared__ float red[32];
    long r = blockIdx.x;
    const float* x = in + r * H_;
    float v0 = x[threadIdx.x];
    float v1 = x[threadIdx.x + 256];
    float sum = block_sum_8w(v0 + v1, red);
    float m = sum * (1.f / 512.f);
    float d0 = v0 - m, d1 = v1 - m;
    __syncthreads();
    float var = block_sum_8w(d0 * d0 + d1 * d1, red) * (1.f / 512.f);
    float inv = rsqrtf(var + 1e-5f);
    float y0 = d0 * inv, y1 = d1 * inv;
    if (s) {
        y0 = y0 * s[threadIdx.x] + b[threadIdx.x];
        y1 = y1 * s[threadIdx.x + 256] + b[threadIdx.x + 256];
    }
    if (do_tanh) { y0 = tanhf(y0); y1 = tanhf(y1); }
    if (out) {
        float* o = out + r * H_;
        o[threadIdx.x] = y0;
        o[threadIdx.x + 256] = y1;
    }
    if (out16) {
        __half* o = out16 + r * H_;
        o[threadIdx.x] = __float2half(y0);
        o[threadIdx.x + 256] = __float2half(y1);
    }
}

// ---------------- parse softmax ----------------
__global__ void softmax_head_kernel(float* __restrict__ head, const int* __restrict__ mask) {
    __shared__ float red[32];
    int bi = blockIdx.x;
    int b = bi >> 8, i = bi & 255;
    float* row = head + (long)bi * L_;
    int j = threadIdx.x;
    float v = (mask[b * L_ + j] != 0) ? row[j] * (1.f / 512.f) : -INFINITY;

    int lane = threadIdx.x & 31, w = threadIdx.x >> 5;
    float m = v;
#pragma unroll
    for (int o = 16; o; o >>= 1) m = fmaxf(m, __shfl_xor_sync(0xffffffffu, m, o));
    if (lane == 0) red[w] = m;
    __syncthreads();
    float t = (lane < 8) ? red[lane] : -INFINITY;
#pragma unroll
    for (int o = 4; o; o >>= 1) t = fmaxf(t, __shfl_xor_sync(0xffffffffu, t, o));
    m = __shfl_sync(0xffffffffu, t, 0);
    __syncthreads();

    float e = (v == -INFINITY) ? 0.f : __expf(v - m);
    float sum = block_sum_8w(e, red);
    float p = (sum > 0.f) ? e / sum : 0.f;
    if (j == i) p = 0.f;
    row[j] = p;
}

// ---------------- head transpose ----------------
__global__ void transpose_kernel(const float* __restrict__ head, float* __restrict__ headT) {
    __shared__ float t[32][33];
    int b = blockIdx.z;
    int i0 = blockIdx.y * 32, j0 = blockIdx.x * 32;
    const float* src = head + (long)b * L_ * L_;
    t[threadIdx.y][threadIdx.x] = src[(long)(i0 + threadIdx.y) * L_ + j0 + threadIdx.x];
    __syncthreads();
    headT[(long)b * L_ * L_ + (long)(j0 + threadIdx.y) * L_ + i0 + threadIdx.x] =
        t[threadIdx.x][threadIdx.y];
}

// ---------------- host orchestration ----------------
#define GSM_SMALL (NSTAGE * (128 * 128 + 64 * 128))     // 73728
#define GSM_BIG   (NSTAGE * (128 * 128 + 128 * 128))    // 98304

static inline void launch_h(const __half* A, const __half* W, const float* bias,
                            const float* resid, float* C, __half* C16, const int* mask,
                            int M, int N, int Kd, int epilogue,
                            int conv_mode = 0, int strideA = -1,
                            int batch = 1, long sA = 0, long sB = 0, long sC = 0) {
    if (strideA < 0) strideA = Kd;
    if (N <= 512) {
        dim3 g((N + 63) / 64, M / 128, batch);
        gemm_h<4, 2, 2, 4><<<g, 256, GSM_SMALL>>>(A, W, bias, resid, C, C16, mask,
                                                  M, N, Kd, strideA, sA, sB, sC,
                                                  epilogue, conv_mode);
    } else {
        dim3 g((N + 127) / 128, M / 128, batch);
        gemm_h<2, 4, 4, 4><<<g, 256, GSM_BIG>>>(A, W, bias, resid, C, C16, mask,
                                                M, N, Kd, strideA, sA, sB, sC,
                                                epilogue, conv_mode);
    }
}

static inline void cvt(const float* src, __half* dst, long n) {
    int n4 = (int)(n / 4);
    cvt_f2h<<<(n4 + 255) / 256, 256>>>(src, dst, n4);
}

extern "C" void kernel_launch(void* const* d_in, const int* in_sizes, int n_in,
                              void* d_out, int out_size) {
    const int*   x        = (const int*)d_in[0];
    const float* emb      = (const float*)d_in[2];
    const float* conv_w   = (const float*)d_in[3];
    const float* conv_b   = (const float*)d_in[4];
    const float* parent_w = (const float*)d_in[5];
    const float* parent_b = (const float*)d_in[6];
    const float* child_w  = (const float*)d_in[7];
    const float* child_b  = (const float*)d_in[8];
    const float* rel_w    = (const float*)d_in[9];
    const float* qkv_w    = (const float*)d_in[10];
    const float* qkv_b    = (const float*)d_in[11];
    const float* out_w    = (const float*)d_in[12];
    const float* out_b    = (const float*)d_in[13];
    const float* ln1_s    = (const float*)d_in[14];
    const float* ln1_b    = (const float*)d_in[15];
    const float* ln2_s    = (const float*)d_in[16];
    const float* ln2_b    = (const float*)d_in[17];
    const float* ff1_w    = (const float*)d_in[18];
    const float* ff1_b    = (const float*)d_in[19];
    const float* ff2_w    = (const float*)d_in[20];
    const float* ff2_b    = (const float*)d_in[21];
    const float* norm_s   = (const float*)d_in[22];
    const float* norm_b   = (const float*)d_in[23];
    const float* out_bias = (const float*)d_in[24];
    float* out = (float*)d_out;

    void *p;
    cudaGetSymbolAddress(&p, g_h);       float*  h      = (float*)p;
    cudaGetSymbolAddress(&p, g_tmp);     float*  tmp    = (float*)p;
    cudaGetSymbolAddress(&p, g_head);    float*  head   = (float*)p;
    cudaGetSymbolAddress(&p, g_headT);   float*  headT  = (float*)p;
    cudaGetSymbolAddress(&p, g_mask);    int*    mask   = (int*)p;
    cudaGetSymbolAddress(&p, g_h16);     __half* h16    = (__half*)p;
    cudaGetSymbolAddress(&p, g_hn16);    __half* hn16   = (__half*)p;
    cudaGetSymbolAddress(&p, g_par16);   __half* par16  = (__half*)p;
    cudaGetSymbolAddress(&p, g_chi16);   __half* chi16  = (__half*)p;
    cudaGetSymbolAddress(&p, g_qkv16);   __half* qkv16  = (__half*)p;
    cudaGetSymbolAddress(&p, g_ctx16);   __half* ctx16  = (__half*)p;
    cudaGetSymbolAddress(&p, g_ff16);    __half* ff16   = (__half*)p;
    cudaGetSymbolAddress(&p, g_convT16); __half* convT16 = (__half*)p;
    cudaGetSymbolAddress(&p, g_qkvw16);  __half* qkvw16 = (__half*)p;
    cudaGetSymbolAddress(&p, g_outw16);  __half* outw16 = (__half*)p;
    cudaGetSymbolAddress(&p, g_ff1w16);  __half* ff1w16 = (__half*)p;
    cudaGetSymbolAddress(&p, g_ff2w16);  __half* ff2w16 = (__half*)p;
    cudaGetSymbolAddress(&p, g_parw16);  __half* parw16 = (__half*)p;
    cudaGetSymbolAddress(&p, g_chiw16);  __half* chiw16 = (__half*)p;
    cudaGetSymbolAddress(&p, g_emb16);   __half* emb16  = (__half*)p;

    cudaFuncSetAttribute(attn_mma, cudaFuncAttributeMaxDynamicSharedMemorySize, ATT_SMEM);
    cudaFuncSetAttribute(gemm_h<4, 2, 2, 4>,
                         cudaFuncAttributeMaxDynamicSharedMemorySize, GSM_SMALL);
    cudaFuncSetAttribute(gemm_h<2, 4, 4, 4>,
                         cudaFuncAttributeMaxDynamicSharedMemorySize, GSM_BIG);

    // ---- weight conversions ----
    convw_transpose16<<<dim3(16, 16, P_ * KW_), dim3(32, 32)>>>(conv_w, convT16);
    cvt(qkv_w, qkvw16, (long)NL_ * 3 * H_ * H_);
    cvt(out_w, outw16, (long)NL_ * H_ * H_);
    cvt(ff1_w, ff1w16, (long)NL_ * DFF_ * H_);
    cvt(ff2_w, ff2w16, (long)NL_ * H_ * DFF_);
    cvt(parent_w, parw16, (long)H_ * H_);
    cvt(child_w, chiw16, (long)H_ * H_);
    cvt(emb, emb16, (long)NTOK_ * H_);

    // ---- embedding + mask ----
    embed_kernel<<<BL_, 256>>>(x, emb, h, h16, mask);

    // ---- parser: conv GEMM (mask fused in producer) -> LN+tanh(fp16 out) ----
    for (int pl = 0; pl < P_; pl++) {
        launch_h(h16, convT16 + (long)pl * H_ * KW_ * H_, conv_b + pl * H_,
                 nullptr, tmp, nullptr, mask, BL_, H_, KW_ * H_, 0,
                 /*conv_mode=*/1, /*strideA=*/H_);
        ln_kernel<<<BL_, 256>>>(tmp, nullptr, h16, nullptr, nullptr, 1);
    }

    // ---- parent / child (fp16 outputs) ----
    launch_h(h16, parw16, parent_b, nullptr, nullptr, par16, mask, BL_, H_, H_, 0);
    launch_h(h16, chiw16, child_b, nullptr, nullptr, chi16, mask, BL_, H_, H_, 0);

    // ---- parse logits + softmax + transpose ----
    launch_h(chi16, par16, nullptr, nullptr, head, nullptr, mask, L_, L_, H_, 0, 0, -1,
             B_, (long)L_ * H_, (long)L_ * H_, (long)L_ * L_);
    softmax_head_kernel<<<BL_, 256>>>(head, mask);
    transpose_kernel<<<dim3(8, 8, B_), dim3(32, 32)>>>(head, headT);

    // ---- transformer ----
    embed_kernel<<<BL_, 256>>>(x, emb, h, h16, mask);
    for (int i = 0; i < NL_; i++) {
        ln_kernel<<<BL_, 256>>>(h, nullptr, hn16, ln1_s + i * H_, ln1_b + i * H_, 0);
        launch_h(hn16, qkvw16 + (long)i * 3 * H_ * H_, qkv_b + i * 3 * H_,
                 nullptr, nullptr, qkv16, mask, BL_, 3 * H_, H_, 0);
        attn_mma<<<dim3(4, NH_, B_), 256, ATT_SMEM>>>(qkv16, head, headT, mask,
                                                      rel_w, i, ctx16);
        launch_h(ctx16, outw16 + (long)i * H_ * H_, out_b + i * H_, h, h, nullptr, mask,
                 BL_, H_, H_, 0);
        ln_kernel<<<BL_, 256>>>(h, nullptr, hn16, ln2_s + i * H_, ln2_b + i * H_, 0);
        launch_h(hn16, ff1w16 + (long)i * DFF_ * H_, ff1_b + i * DFF_,
                 nullptr, nullptr, ff16, mask, BL_, DFF_, H_, 1);
        launch_h(ff16, ff2w16 + (long)i * H_ * DFF_, ff2_b + i * H_, h, h, nullptr, mask,
                 BL_, H_, DFF_, 0);
    }

    // ---- final LN + tied output ----
    ln_kernel<<<BL_, 256>>>(h, nullptr, hn16, norm_s, norm_b, 0);
    launch_h(hn16, emb16, out_bias, nullptr, out, nullptr, mask, BL_, NTOK_, H_, 0);
}